// round 1
// baseline (speedup 1.0000x reference)
#include <cuda_runtime.h>
#include <cuda_bf16.h>
#include <math.h>

#define B_ 16
#define T_ 2048
#define N_ 64
#define F_ 1025
#define GATE_H 64

// Output layout (flattened tuple in order)
#define SEED_OFF 0
#define GCN_OFF  2097152
#define FREQ_OFF 4194304
#define IMP_OFF  6291456
#define COMP_OFF 8388608
#define GATE_OFF 10485760
#define ADJ_OFF  14680064

// Scratch (static device arrays: allowed)
__device__ float g_ffill[B_ * T_ * N_];
__device__ unsigned char g_fav[B_ * T_ * N_];
__device__ float g_adj[N_ * N_];
__device__ float g_preb1[N_ * GATE_H];

__device__ __forceinline__ float gelu_t(float x) {
    // tanh-approx gelu (matches jax.nn.gelu approximate=True), robust at +/-inf
    float x2 = x * x;
    float b = x * fmaf(0.0713548162726f, x2, 1.59576912161f); // = 2*sqrt(2/pi)*(x+0.044715x^3)
    float e = __expf(b);
    float r = __fdividef(2.0f, e + 1.0f);
    float t = 1.0f - r;                    // tanh
    float hx = 0.5f * x;
    return fmaf(hx, t, hx);
}

// ---------------------------------------------------------------------------
// Kernel 1: warm-start fill (chunked scan). One block per b, 1024 threads =
// 16 chunks x 64 nodes. Forward fill -> scratch; backward pass combines.
// ---------------------------------------------------------------------------
__global__ void __launch_bounds__(1024) fill_kernel(
    const float* __restrict__ x, const float* __restrict__ mask,
    float* __restrict__ seed)
{
    __shared__ float sLast[16][64], sFirst[16][64];
    __shared__ unsigned char sHas[16][64];
    __shared__ float sPrefV[16][64], sSufV[16][64];
    __shared__ unsigned char sPrefH[16][64], sSufH[16][64];

    const int CH = T_ / 16; // 128
    int b = blockIdx.x, tid = threadIdx.x;
    int c = tid >> 6, n = tid & 63;
    int base = (b * T_ + c * CH) * N_ + n;

    // Phase 1: chunk summaries
    float lastv = 0.f, firstv = 0.f; bool has = false;
    #pragma unroll 4
    for (int t = 0; t < CH; ++t) {
        int idx = base + t * N_;
        float v = x[idx];
        float m = mask[idx];
        bool obs = (m == 0.f);
        if (obs) { if (!has) firstv = v; lastv = v; has = true; }
    }
    sLast[c][n] = lastv; sFirst[c][n] = firstv; sHas[c][n] = (unsigned char)has;
    __syncthreads();

    // Phase 2: exclusive prefix (fwd) / suffix (bwd) over chunks per node
    if (tid < 64) {
        float pv = 0.f; bool ph = false;
        #pragma unroll
        for (int cc = 0; cc < 16; ++cc) {
            sPrefV[cc][tid] = pv; sPrefH[cc][tid] = (unsigned char)ph;
            if (sHas[cc][tid]) { pv = sLast[cc][tid]; ph = true; }
        }
        float sv = 0.f; bool sh = false;
        #pragma unroll
        for (int cc = 15; cc >= 0; --cc) {
            sSufV[cc][tid] = sv; sSufH[cc][tid] = (unsigned char)sh;
            if (sHas[cc][tid]) { sv = sFirst[cc][tid]; sh = true; }
        }
    }
    __syncthreads();

    // Phase 3a: forward fill -> scratch
    float fv = sPrefV[c][n]; bool fh = (bool)sPrefH[c][n];
    #pragma unroll 4
    for (int t = 0; t < CH; ++t) {
        int idx = base + t * N_;
        float v = x[idx]; float m = mask[idx];
        bool obs = (m == 0.f);
        if (obs) { fv = v; fh = true; }
        g_ffill[idx] = fv;
        g_fav[idx] = (unsigned char)fh;
    }
    // Phase 3b: backward fill + combine
    float bv = sSufV[c][n]; bool bh = (bool)sSufH[c][n];
    #pragma unroll 4
    for (int t = CH - 1; t >= 0; --t) {
        int idx = base + t * N_;
        float v = x[idx]; float m = mask[idx];
        bool obs = (m == 0.f);
        if (obs) { bv = v; bh = true; }
        float out;
        if (obs) {
            out = v;
        } else {
            float ff = g_ffill[idx];
            bool fa = (bool)g_fav[idx];
            if (fa && bh)      out = 0.5f * (ff + bv);
            else if (fa)       out = ff;
            else if (bh)       out = bv;
            else               out = 0.f;
        }
        seed[idx] = out;
    }
}

// ---------------------------------------------------------------------------
// Kernel 2: adjacency (relu+softmax of emb@emb^T) + rate-embed pre-bias
// ---------------------------------------------------------------------------
__global__ void __launch_bounds__(64) adj_kernel(
    const float* __restrict__ emb, const int* __restrict__ rate_id,
    const float* __restrict__ rate_table, const float* __restrict__ gw1,
    const float* __restrict__ gb1, float* __restrict__ out_adj)
{
    __shared__ float sE[64 * 32];
    int tid = threadIdx.x;
    for (int i = tid; i < 64 * 32; i += 64) sE[i] = emb[i];
    __syncthreads();

    float sc[64];
    float mx = -1e30f;
    #pragma unroll
    for (int m = 0; m < 64; ++m) {
        float d = 0.f;
        #pragma unroll
        for (int h = 0; h < 32; ++h) d = fmaf(sE[tid * 32 + h], sE[m * 32 + h], d);
        d = fmaxf(d, 0.f);
        sc[m] = d; mx = fmaxf(mx, d);
    }
    float sum = 0.f;
    #pragma unroll
    for (int m = 0; m < 64; ++m) { float e = __expf(sc[m] - mx); sc[m] = e; sum += e; }
    float inv = 1.0f / sum;
    #pragma unroll
    for (int m = 0; m < 64; ++m) {
        float a = sc[m] * inv;
        g_adj[tid * 64 + m] = a;
        out_adj[tid * 64 + m] = a;
    }
    // pre-bias: gb1[j] + sum_e rate_table[rid][e] * gw1[6+e][j]
    int rid = rate_id[tid];
    for (int j = 0; j < 64; ++j) {
        float v = gb1[j];
        #pragma unroll
        for (int e = 0; e < 16; ++e)
            v = fmaf(rate_table[rid * 16 + e], gw1[(6 + e) * 64 + j], v);
        g_preb1[tid * 64 + j] = v;
    }
}

// ---------------------------------------------------------------------------
// Kernel 3: rfft -> filter -> irfft via packed (2 real signals) radix-2 FFT.
// Forward DIF (natural in), filter in bit-reversed domain, inverse DIT
// (natural out). Imag of bins 0 and N/2 dropped (pocketfft c2r semantics).
// ---------------------------------------------------------------------------
__global__ void __launch_bounds__(256) fft_kernel(
    const float* __restrict__ seed, const float* __restrict__ fre,
    const float* __restrict__ fim, float* __restrict__ xfreq)
{
    __shared__ float re[2048], im[2048], twr[1024], twi[1024];
    int tid = threadIdx.x;
    int b = blockIdx.x >> 5;
    int p = blockIdx.x & 31;
    int n0 = p * 2;
    const float* src = seed + (size_t)b * T_ * N_ + n0;

    for (int j = tid; j < 1024; j += 256) {
        float s, c;
        sincosf(-6.28318530717958647692f * (float)j * (1.0f / 2048.0f), &s, &c);
        twr[j] = c; twi[j] = s;
    }
    for (int t = tid; t < 2048; t += 256) {
        float2 v = *(const float2*)(src + (size_t)t * N_);
        re[t] = v.x; im[t] = v.y;
    }

    // Forward DIF
    for (int s = 10; s >= 0; --s) {
        int half = 1 << s;
        __syncthreads();
        for (int bi = tid; bi < 1024; bi += 256) {
            int j = bi & (half - 1);
            int i1 = ((bi >> s) << (s + 1)) | j;
            int i2 = i1 + half;
            int tj = j << (10 - s);
            float wr = twr[tj], wi = twi[tj];
            float ar = re[i1], ai = im[i1], br = re[i2], b2 = im[i2];
            re[i1] = ar + br; im[i1] = ai + b2;
            float dr = ar - br, di = ai - b2;
            re[i2] = dr * wr - di * wi;
            im[i2] = dr * wi + di * wr;
        }
    }
    __syncthreads();

    // Filter in bit-reversed domain; unpack 2 real spectra, apply H, repack
    for (int k = tid; k <= 1024; k += 256) {
        int km = (2048 - k) & 2047;
        int pk = __brev(k) >> 21;
        int pm = __brev(km) >> 21;
        float zr = re[pk], zi = im[pk];
        float yr = re[pm], yi = im[pm];
        float x1r = 0.5f * (zr + yr), x1i = 0.5f * (zi - yi);
        float x2r = 0.5f * (zi + yi), x2i = 0.5f * (yr - zr);
        float h1r = fre[(size_t)k * N_ + n0],     h1i = fim[(size_t)k * N_ + n0];
        float h2r = fre[(size_t)k * N_ + n0 + 1], h2i = fim[(size_t)k * N_ + n0 + 1];
        float y1r = x1r * h1r - x1i * h1i, y1i = x1r * h1i + x1i * h1r;
        float y2r = x2r * h2r - x2i * h2i, y2i = x2r * h2i + x2i * h2r;
        if (k == 0 || k == 1024) { y1i = 0.f; y2i = 0.f; }
        re[pk] = y1r - y2i; im[pk] = y1i + y2r;
        if (k > 0 && k < 1024) { re[pm] = y1r + y2i; im[pm] = y2r - y1i; }
    }

    // Inverse DIT
    for (int s = 0; s <= 10; ++s) {
        int half = 1 << s;
        __syncthreads();
        for (int bi = tid; bi < 1024; bi += 256) {
            int j = bi & (half - 1);
            int i1 = ((bi >> s) << (s + 1)) | j;
            int i2 = i1 + half;
            int tj = j << (10 - s);
            float wr = twr[tj], wi = -twi[tj];
            float br = re[i2], b2 = im[i2];
            float tr = br * wr - b2 * wi, ti = br * wi + b2 * wr;
            float ar = re[i1], ai = im[i1];
            re[i1] = ar + tr; im[i1] = ai + ti;
            re[i2] = ar - tr; im[i2] = ai - ti;
        }
    }
    __syncthreads();

    float* dst = xfreq + (size_t)b * T_ * N_ + n0;
    const float scl = 1.0f / 2048.0f;
    for (int t = tid; t < 2048; t += 256) {
        float2 v; v.x = re[t] * scl; v.y = im[t] * scl;
        *(float2*)(dst + (size_t)t * N_) = v;
    }
}

// ---------------------------------------------------------------------------
// Kernel 4: fused GCN (scalar phi + adjacency matvec) + gate MLP + outputs.
// Block = 256 threads = 4 (b,t) rows x 64 nodes; each thread owns one element.
// ---------------------------------------------------------------------------
__global__ void __launch_bounds__(256, 2) fused_kernel(
    const float* __restrict__ seed, const float* __restrict__ mask,
    const float* __restrict__ xin, const float* __restrict__ xfreq,
    const float* __restrict__ gw1, const float* __restrict__ gw2,
    const float* __restrict__ gb2, const float* __restrict__ gw3,
    const float* __restrict__ gb3,
    const float* __restrict__ gcw1, const float* __restrict__ gcb1,
    const float* __restrict__ gcw2, const float* __restrict__ gcb2,
    float* __restrict__ out_gcn, float* __restrict__ out_imp,
    float* __restrict__ out_comp, float* __restrict__ out_gate)
{
    __shared__ float sA[64 * 65];    // padded adjacency
    __shared__ float sP1t[64 * 64];  // preb1 transposed [j][n]
    __shared__ float sW1[6 * 64];
    __shared__ float sW2[64 * 64];
    __shared__ float sW3[128];
    __shared__ float sB2[64];
    __shared__ float sGc[96];        // gcn w1(32), b1(32), w2(32)
    __shared__ float sPm[4 * 64];    // phi values per row
    __shared__ float sConst[3];      // gcn_b2, gb3[0], gb3[1]

    int tid = threadIdx.x;
    for (int i = tid; i < 4096; i += 256) sA[(i >> 6) * 65 + (i & 63)] = g_adj[i];
    for (int i = tid; i < 4096; i += 256) sP1t[(i & 63) * 64 + (i >> 6)] = g_preb1[i];
    for (int i = tid; i < 384; i += 256) sW1[i] = gw1[i];
    for (int i = tid; i < 4096; i += 256) sW2[i] = gw2[i];
    if (tid < 128) sW3[tid] = gw3[tid];
    if (tid < 64) sB2[tid] = gb2[tid];
    if (tid < 32) { sGc[tid] = gcw1[tid]; sGc[32 + tid] = gcb1[tid]; sGc[64 + tid] = gcw2[tid]; }
    if (tid == 0) { sConst[0] = gcb2[0]; sConst[1] = gb3[0]; sConst[2] = gb3[1]; }
    __syncthreads();

    int r = tid >> 6;
    int n = tid & 63;
    int row = blockIdx.x * 4 + r;       // in [0, B*T)
    int idx = row * N_ + n;

    float s  = seed[idx];
    float mm = mask[idx];
    float xf = xfreq[idx];
    float xi = xin[idx];

    // phi(s) = sum_h w2[h] * gelu(s*w1[h] + b1[h])
    float pv = 0.f;
    #pragma unroll
    for (int h = 0; h < 32; ++h)
        pv = fmaf(sGc[64 + h], gelu_t(fmaf(s, sGc[h], sGc[32 + h])), pv);
    sPm[r * 64 + n] = pv;
    __syncthreads();

    // x_gcn[n] = sum_m A[n,m] * phi_m + gcn_b2
    float xg = sConst[0];
    #pragma unroll 8
    for (int m = 0; m < 64; ++m)
        xg = fmaf(sA[n * 65 + m], sPm[r * 64 + m], xg);

    float f0 = s, f1 = mm, f2 = xg, f3 = xf, f4 = xg - s, f5 = xf - s;

    // Layer 1 (6 features + precomputed rate-bias), h1 in registers
    float h1[64];
    const float4* W1v = (const float4*)sW1;
    #pragma unroll
    for (int jq = 0; jq < 16; ++jq) {
        int j = jq * 4;
        float a0 = sP1t[(j + 0) * 64 + n];
        float a1 = sP1t[(j + 1) * 64 + n];
        float a2 = sP1t[(j + 2) * 64 + n];
        float a3 = sP1t[(j + 3) * 64 + n];
        float4 w;
        w = W1v[0 * 16 + jq]; a0 = fmaf(f0, w.x, a0); a1 = fmaf(f0, w.y, a1); a2 = fmaf(f0, w.z, a2); a3 = fmaf(f0, w.w, a3);
        w = W1v[1 * 16 + jq]; a0 = fmaf(f1, w.x, a0); a1 = fmaf(f1, w.y, a1); a2 = fmaf(f1, w.z, a2); a3 = fmaf(f1, w.w, a3);
        w = W1v[2 * 16 + jq]; a0 = fmaf(f2, w.x, a0); a1 = fmaf(f2, w.y, a1); a2 = fmaf(f2, w.z, a2); a3 = fmaf(f2, w.w, a3);
        w = W1v[3 * 16 + jq]; a0 = fmaf(f3, w.x, a0); a1 = fmaf(f3, w.y, a1); a2 = fmaf(f3, w.z, a2); a3 = fmaf(f3, w.w, a3);
        w = W1v[4 * 16 + jq]; a0 = fmaf(f4, w.x, a0); a1 = fmaf(f4, w.y, a1); a2 = fmaf(f4, w.z, a2); a3 = fmaf(f4, w.w, a3);
        w = W1v[5 * 16 + jq]; a0 = fmaf(f5, w.x, a0); a1 = fmaf(f5, w.y, a1); a2 = fmaf(f5, w.z, a2); a3 = fmaf(f5, w.w, a3);
        h1[j + 0] = gelu_t(a0);
        h1[j + 1] = gelu_t(a1);
        h1[j + 2] = gelu_t(a2);
        h1[j + 3] = gelu_t(a3);
    }

    // Layer 2 (64x64) + layer 3 (64x2) fused
    float lg0 = sConst[1], lg1 = sConst[2];
    for (int jq = 0; jq < 16; ++jq) {
        const float4* W2v = (const float4*)sW2 + jq;
        float a0 = 0.f, a1 = 0.f, a2 = 0.f, a3 = 0.f;
        #pragma unroll
        for (int k = 0; k < 64; ++k) {
            float4 w = W2v[k * 16];
            a0 = fmaf(h1[k], w.x, a0);
            a1 = fmaf(h1[k], w.y, a1);
            a2 = fmaf(h1[k], w.z, a2);
            a3 = fmaf(h1[k], w.w, a3);
        }
        int j = jq * 4;
        float h20 = gelu_t(a0 + sB2[j + 0]);
        float h21 = gelu_t(a1 + sB2[j + 1]);
        float h22 = gelu_t(a2 + sB2[j + 2]);
        float h23 = gelu_t(a3 + sB2[j + 3]);
        lg0 = fmaf(h20, sW3[(j + 0) * 2], lg0); lg1 = fmaf(h20, sW3[(j + 0) * 2 + 1], lg1);
        lg0 = fmaf(h21, sW3[(j + 1) * 2], lg0); lg1 = fmaf(h21, sW3[(j + 1) * 2 + 1], lg1);
        lg0 = fmaf(h22, sW3[(j + 2) * 2], lg0); lg1 = fmaf(h22, sW3[(j + 2) * 2 + 1], lg1);
        lg0 = fmaf(h23, sW3[(j + 3) * 2], lg0); lg1 = fmaf(h23, sW3[(j + 3) * 2 + 1], lg1);
    }

    // 2-way softmax
    float mx = fmaxf(lg0, lg1);
    float e0 = __expf(lg0 - mx), e1 = __expf(lg1 - mx);
    float inv = __fdividef(1.0f, e0 + e1);
    float g0 = e0 * inv, g1 = e1 * inv;

    float imputed = fmaf(g0, xg, g1 * xf);
    float complete = (mm != 0.f) ? imputed : xi;

    out_gcn[idx] = xg;
    out_imp[idx] = imputed;
    out_comp[idx] = complete;
    float2 gv; gv.x = g0; gv.y = g1;
    *(float2*)(out_gate + (size_t)idx * 2) = gv;
}

// ---------------------------------------------------------------------------
extern "C" void kernel_launch(void* const* d_in, const int* in_sizes, int n_in,
                              void* d_out, int out_size)
{
    const float* x     = (const float*)d_in[0];
    const float* mask  = (const float*)d_in[1];
    const int*   rid   = (const int*)  d_in[2];
    const float* emb   = (const float*)d_in[3];
    const float* gcw1  = (const float*)d_in[4];
    const float* gcb1  = (const float*)d_in[5];
    const float* gcw2  = (const float*)d_in[6];
    const float* gcb2  = (const float*)d_in[7];
    const float* fre   = (const float*)d_in[8];
    const float* fim   = (const float*)d_in[9];
    const float* rtab  = (const float*)d_in[10];
    const float* gw1   = (const float*)d_in[11];
    const float* gb1   = (const float*)d_in[12];
    const float* gw2   = (const float*)d_in[13];
    const float* gb2   = (const float*)d_in[14];
    const float* gw3   = (const float*)d_in[15];
    const float* gb3   = (const float*)d_in[16];
    float* out = (float*)d_out;

    fill_kernel<<<B_, 1024>>>(x, mask, out + SEED_OFF);
    adj_kernel<<<1, 64>>>(emb, rid, rtab, gw1, gb1, out + ADJ_OFF);
    fft_kernel<<<B_ * N_ / 2, 256>>>(out + SEED_OFF, fre, fim, out + FREQ_OFF);
    fused_kernel<<<B_ * T_ / 4, 256>>>(
        out + SEED_OFF, mask, x, out + FREQ_OFF,
        gw1, gw2, gb2, gw3, gb3,
        gcw1, gcb1, gcw2, gcb2,
        out + GCN_OFF, out + IMP_OFF, out + COMP_OFF, out + GATE_OFF);
}

// round 2
// speedup vs baseline: 1.1021x; 1.1021x over previous
#include <cuda_runtime.h>
#include <cuda_bf16.h>
#include <math.h>

#define B_ 16
#define T_ 2048
#define N_ 64
#define GATE_H 64

// Output layout (flattened tuple in order)
#define SEED_OFF 0
#define GCN_OFF  2097152
#define FREQ_OFF 4194304
#define IMP_OFF  6291456
#define COMP_OFF 8388608
#define GATE_OFF 10485760
#define ADJ_OFF  14680064

typedef unsigned long long u64;

// Scratch (static device arrays: allowed)
__device__ float  g_ffill[B_ * T_ * N_];
__device__ unsigned char g_fav[B_ * T_ * N_];
__device__ float  g_adj[N_ * N_];
__device__ float2 g_preb1p[32 * N_];   // [j_pair][n] -> (preb1[n][2j], preb1[n][2j+1])

// ---- packed f32x2 helpers (sm_100+ PTX) -----------------------------------
__device__ __forceinline__ u64 pk2(float lo, float hi) {
    u64 r; asm("mov.b64 %0, {%1, %2};" : "=l"(r) : "f"(lo), "f"(hi)); return r;
}
__device__ __forceinline__ void upk2(u64 v, float& lo, float& hi) {
    asm("mov.b64 {%0, %1}, %2;" : "=f"(lo), "=f"(hi) : "l"(v));
}
__device__ __forceinline__ u64 ffma2(u64 a, u64 b, u64 c) {
    u64 d; asm("fma.rn.f32x2 %0, %1, %2, %3;" : "=l"(d) : "l"(a), "l"(b), "l"(c)); return d;
}

__device__ __forceinline__ float gelu_t(float x) {
    // tanh-approx gelu (matches jax.nn.gelu), robust at +/-inf
    float x2 = x * x;
    float b = x * fmaf(0.0713548162726f, x2, 1.59576912161f);
    float e = __expf(b);
    float r = __fdividef(2.0f, e + 1.0f);
    float t = 1.0f - r;
    float hx = 0.5f * x;
    return fmaf(hx, t, hx);
}

// ---------------------------------------------------------------------------
// Kernel 1: warm-start fill (chunked scan)
// ---------------------------------------------------------------------------
__global__ void __launch_bounds__(1024) fill_kernel(
    const float* __restrict__ x, const float* __restrict__ mask,
    float* __restrict__ seed)
{
    __shared__ float sLast[16][64], sFirst[16][64];
    __shared__ unsigned char sHas[16][64];
    __shared__ float sPrefV[16][64], sSufV[16][64];
    __shared__ unsigned char sPrefH[16][64], sSufH[16][64];

    const int CH = T_ / 16;
    int b = blockIdx.x, tid = threadIdx.x;
    int c = tid >> 6, n = tid & 63;
    int base = (b * T_ + c * CH) * N_ + n;

    float lastv = 0.f, firstv = 0.f; bool has = false;
    #pragma unroll 4
    for (int t = 0; t < CH; ++t) {
        int idx = base + t * N_;
        float v = x[idx];
        bool obs = (mask[idx] == 0.f);
        if (obs) { if (!has) firstv = v; lastv = v; has = true; }
    }
    sLast[c][n] = lastv; sFirst[c][n] = firstv; sHas[c][n] = (unsigned char)has;
    __syncthreads();

    if (tid < 64) {
        float pv = 0.f; bool ph = false;
        #pragma unroll
        for (int cc = 0; cc < 16; ++cc) {
            sPrefV[cc][tid] = pv; sPrefH[cc][tid] = (unsigned char)ph;
            if (sHas[cc][tid]) { pv = sLast[cc][tid]; ph = true; }
        }
        float sv = 0.f; bool sh = false;
        #pragma unroll
        for (int cc = 15; cc >= 0; --cc) {
            sSufV[cc][tid] = sv; sSufH[cc][tid] = (unsigned char)sh;
            if (sHas[cc][tid]) { sv = sFirst[cc][tid]; sh = true; }
        }
    }
    __syncthreads();

    float fv = sPrefV[c][n]; bool fh = (bool)sPrefH[c][n];
    #pragma unroll 4
    for (int t = 0; t < CH; ++t) {
        int idx = base + t * N_;
        float v = x[idx];
        bool obs = (mask[idx] == 0.f);
        if (obs) { fv = v; fh = true; }
        g_ffill[idx] = fv;
        g_fav[idx] = (unsigned char)fh;
    }
    float bv = sSufV[c][n]; bool bh = (bool)sSufH[c][n];
    #pragma unroll 4
    for (int t = CH - 1; t >= 0; --t) {
        int idx = base + t * N_;
        float v = x[idx];
        bool obs = (mask[idx] == 0.f);
        if (obs) { bv = v; bh = true; }
        float out;
        if (obs) out = v;
        else {
            float ff = g_ffill[idx];
            bool fa = (bool)g_fav[idx];
            if (fa && bh)      out = 0.5f * (ff + bv);
            else if (fa)       out = ff;
            else if (bh)       out = bv;
            else               out = 0.f;
        }
        seed[idx] = out;
    }
}

// ---------------------------------------------------------------------------
// Kernel 2: adjacency + rate-embed pre-bias (paired layout)
// ---------------------------------------------------------------------------
__global__ void __launch_bounds__(64) adj_kernel(
    const float* __restrict__ emb, const int* __restrict__ rate_id,
    const float* __restrict__ rate_table, const float* __restrict__ gw1,
    const float* __restrict__ gb1, float* __restrict__ out_adj)
{
    __shared__ float sE[64 * 32];
    int tid = threadIdx.x;
    for (int i = tid; i < 64 * 32; i += 64) sE[i] = emb[i];
    __syncthreads();

    float sc[64];
    float mx = -1e30f;
    #pragma unroll
    for (int m = 0; m < 64; ++m) {
        float d = 0.f;
        #pragma unroll
        for (int h = 0; h < 32; ++h) d = fmaf(sE[tid * 32 + h], sE[m * 32 + h], d);
        d = fmaxf(d, 0.f);
        sc[m] = d; mx = fmaxf(mx, d);
    }
    float sum = 0.f;
    #pragma unroll
    for (int m = 0; m < 64; ++m) { float e = __expf(sc[m] - mx); sc[m] = e; sum += e; }
    float inv = 1.0f / sum;
    #pragma unroll
    for (int m = 0; m < 64; ++m) {
        float a = sc[m] * inv;
        g_adj[tid * 64 + m] = a;
        out_adj[tid * 64 + m] = a;
    }
    int rid = rate_id[tid];
    for (int j2 = 0; j2 < 32; ++j2) {
        float v0 = gb1[2 * j2], v1 = gb1[2 * j2 + 1];
        #pragma unroll
        for (int e = 0; e < 16; ++e) {
            float rt = rate_table[rid * 16 + e];
            v0 = fmaf(rt, gw1[(6 + e) * 64 + 2 * j2], v0);
            v1 = fmaf(rt, gw1[(6 + e) * 64 + 2 * j2 + 1], v1);
        }
        g_preb1p[j2 * 64 + tid] = make_float2(v0, v1);
    }
}

// ---------------------------------------------------------------------------
// Kernel 3: packed-pair radix-2 FFT filter (unchanged)
// ---------------------------------------------------------------------------
__global__ void __launch_bounds__(256) fft_kernel(
    const float* __restrict__ seed, const float* __restrict__ fre,
    const float* __restrict__ fim, float* __restrict__ xfreq)
{
    __shared__ float re[2048], im[2048], twr[1024], twi[1024];
    int tid = threadIdx.x;
    int b = blockIdx.x >> 5;
    int p = blockIdx.x & 31;
    int n0 = p * 2;
    const float* src = seed + (size_t)b * T_ * N_ + n0;

    for (int j = tid; j < 1024; j += 256) {
        float s, c;
        sincosf(-6.28318530717958647692f * (float)j * (1.0f / 2048.0f), &s, &c);
        twr[j] = c; twi[j] = s;
    }
    for (int t = tid; t < 2048; t += 256) {
        float2 v = *(const float2*)(src + (size_t)t * N_);
        re[t] = v.x; im[t] = v.y;
    }

    for (int s = 10; s >= 0; --s) {
        int half = 1 << s;
        __syncthreads();
        for (int bi = tid; bi < 1024; bi += 256) {
            int j = bi & (half - 1);
            int i1 = ((bi >> s) << (s + 1)) | j;
            int i2 = i1 + half;
            int tj = j << (10 - s);
            float wr = twr[tj], wi = twi[tj];
            float ar = re[i1], ai = im[i1], br = re[i2], b2 = im[i2];
            re[i1] = ar + br; im[i1] = ai + b2;
            float dr = ar - br, di = ai - b2;
            re[i2] = dr * wr - di * wi;
            im[i2] = dr * wi + di * wr;
        }
    }
    __syncthreads();

    for (int k = tid; k <= 1024; k += 256) {
        int km = (2048 - k) & 2047;
        int pk = __brev(k) >> 21;
        int pm = __brev(km) >> 21;
        float zr = re[pk], zi = im[pk];
        float yr = re[pm], yi = im[pm];
        float x1r = 0.5f * (zr + yr), x1i = 0.5f * (zi - yi);
        float x2r = 0.5f * (zi + yi), x2i = 0.5f * (yr - zr);
        float h1r = fre[(size_t)k * N_ + n0],     h1i = fim[(size_t)k * N_ + n0];
        float h2r = fre[(size_t)k * N_ + n0 + 1], h2i = fim[(size_t)k * N_ + n0 + 1];
        float y1r = x1r * h1r - x1i * h1i, y1i = x1r * h1i + x1i * h1r;
        float y2r = x2r * h2r - x2i * h2i, y2i = x2r * h2i + x2i * h2r;
        if (k == 0 || k == 1024) { y1i = 0.f; y2i = 0.f; }
        re[pk] = y1r - y2i; im[pk] = y1i + y2r;
        if (k > 0 && k < 1024) { re[pm] = y1r + y2i; im[pm] = y2r - y1i; }
    }

    for (int s = 0; s <= 10; ++s) {
        int half = 1 << s;
        __syncthreads();
        for (int bi = tid; bi < 1024; bi += 256) {
            int j = bi & (half - 1);
            int i1 = ((bi >> s) << (s + 1)) | j;
            int i2 = i1 + half;
            int tj = j << (10 - s);
            float wr = twr[tj], wi = -twi[tj];
            float br = re[i2], b2 = im[i2];
            float tr = br * wr - b2 * wi, ti = br * wi + b2 * wr;
            float ar = re[i1], ai = im[i1];
            re[i1] = ar + tr; im[i1] = ai + ti;
            re[i2] = ar - tr; im[i2] = ai - ti;
        }
    }
    __syncthreads();

    float* dst = xfreq + (size_t)b * T_ * N_ + n0;
    const float scl = 1.0f / 2048.0f;
    for (int t = tid; t < 2048; t += 256) {
        float2 v; v.x = re[t] * scl; v.y = im[t] * scl;
        *(float2*)(dst + (size_t)t * N_) = v;
    }
}

// ---------------------------------------------------------------------------
// Kernel 4 v2: block-tiled, f32x2-packed fused GCN + gate MLP.
// Phase A: 256 threads x 1 element -> feats + layer1 -> hs[64][256] (smem).
// Phase B: 32 rowgrp x 8 jgrp, each thread 8 rows x 8 cols of layer2 GEMM,
//          packed FFMA2; logits reduced over j-lanes via shfl.xor.
// ---------------------------------------------------------------------------
#define SMEM_BYTES 106496

__global__ void __launch_bounds__(256, 1) fused_kernel(
    const float* __restrict__ seed, const float* __restrict__ mask,
    const float* __restrict__ xin, const float* __restrict__ xfreq,
    const float* __restrict__ gw1, const float* __restrict__ gw2,
    const float* __restrict__ gb2, const float* __restrict__ gw3,
    const float* __restrict__ gb3,
    const float* __restrict__ gcw1, const float* __restrict__ gcb1,
    const float* __restrict__ gcw2, const float* __restrict__ gcb2,
    float* __restrict__ out_gcn, float* __restrict__ out_imp,
    float* __restrict__ out_comp, float* __restrict__ out_gate)
{
    extern __shared__ float sm[];
    float* hs   = sm;               // [64][256]  65536B
    float* sW2  = hs  + 64 * 256;   // [64][64]   16384B
    float* sA   = sW2 + 64 * 64;    // [64][65]   16640B
    float* sW1  = sA  + 64 * 65;    // [6][64]    1536B
    float* sW3  = sW1 + 384;        // 512B
    float* sB2  = sW3 + 128;        // 256B
    float* sGc  = sB2 + 64;         // 384B
    float* sCst = sGc + 96;         // 16B
    float* sPm  = sCst + 4;         // [4][64]
    float* sXg  = sPm + 256;
    float* sXf  = sXg + 256;
    float* sMm  = sXf + 256;
    float* sXi  = sMm + 256;

    int tid = threadIdx.x;

    // ---- stage weights ----
    for (int i = tid; i < 4096; i += 256) sW2[i] = gw2[i];
    for (int i = tid; i < 4096; i += 256) sA[(i >> 6) * 65 + (i & 63)] = g_adj[i];
    for (int i = tid; i < 384; i += 256) sW1[i] = gw1[i];
    if (tid < 128) sW3[tid] = gw3[tid];
    if (tid < 64) sB2[tid] = gb2[tid];
    if (tid < 32) { sGc[tid] = gcw1[tid]; sGc[32 + tid] = gcb1[tid]; sGc[64 + tid] = gcw2[tid]; }
    if (tid == 0) { sCst[0] = gcb2[0]; sCst[1] = gb3[0]; sCst[2] = gb3[1]; }

    // ---- Phase A: per-element feats + layer1 ----
    int n = tid & 63;
    int r = tid >> 6;                       // 0..3
    int gidx = blockIdx.x * 256 + tid;      // global element

    float s  = seed[gidx];
    float mm = mask[gidx];
    float xf = xfreq[gidx];
    float xi = xin[gidx];
    __syncthreads();   // staging done (loads above are pre-sync safe: s/mm from gmem)

    // phi(s)
    float pv = 0.f;
    #pragma unroll
    for (int h = 0; h < 32; ++h)
        pv = fmaf(sGc[64 + h], gelu_t(fmaf(s, sGc[h], sGc[32 + h])), pv);
    sPm[r * 64 + n] = pv;
    __syncthreads();

    // x_gcn: A[n,:] . phi
    float xg = sCst[0];
    #pragma unroll 8
    for (int m = 0; m < 64; ++m)
        xg = fmaf(sA[n * 65 + m], sPm[r * 64 + m], xg);

    sXg[tid] = xg; sXf[tid] = xf; sMm[tid] = mm; sXi[tid] = xi;
    out_gcn[gidx] = xg;

    // packed feature broadcasts
    u64 u0 = pk2(s, s), u1 = pk2(mm, mm), u2 = pk2(xg, xg);
    u64 u3 = pk2(xf, xf), u4 = pk2(xg - s, xg - s), u5 = pk2(xf - s, xf - s);

    // layer1: 4 j per iter (2 pairs)
    const float4* W1v = (const float4*)sW1;
    #pragma unroll
    for (int jq = 0; jq < 16; ++jq) {
        float2 pA = g_preb1p[(2 * jq) * 64 + n];
        float2 pB = g_preb1p[(2 * jq + 1) * 64 + n];
        u64 a0 = pk2(pA.x, pA.y);
        u64 a1 = pk2(pB.x, pB.y);
        float4 w;
        u64 wp;
        w = W1v[0 * 16 + jq]; wp = pk2(w.x, w.y); a0 = ffma2(u0, wp, a0); wp = pk2(w.z, w.w); a1 = ffma2(u0, wp, a1);
        w = W1v[1 * 16 + jq]; wp = pk2(w.x, w.y); a0 = ffma2(u1, wp, a0); wp = pk2(w.z, w.w); a1 = ffma2(u1, wp, a1);
        w = W1v[2 * 16 + jq]; wp = pk2(w.x, w.y); a0 = ffma2(u2, wp, a0); wp = pk2(w.z, w.w); a1 = ffma2(u2, wp, a1);
        w = W1v[3 * 16 + jq]; wp = pk2(w.x, w.y); a0 = ffma2(u3, wp, a0); wp = pk2(w.z, w.w); a1 = ffma2(u3, wp, a1);
        w = W1v[4 * 16 + jq]; wp = pk2(w.x, w.y); a0 = ffma2(u4, wp, a0); wp = pk2(w.z, w.w); a1 = ffma2(u4, wp, a1);
        w = W1v[5 * 16 + jq]; wp = pk2(w.x, w.y); a0 = ffma2(u5, wp, a0); wp = pk2(w.z, w.w); a1 = ffma2(u5, wp, a1);
        float v0, v1, v2, v3;
        upk2(a0, v0, v1); upk2(a1, v2, v3);
        hs[(4 * jq + 0) * 256 + tid] = gelu_t(v0);
        hs[(4 * jq + 1) * 256 + tid] = gelu_t(v1);
        hs[(4 * jq + 2) * 256 + tid] = gelu_t(v2);
        hs[(4 * jq + 3) * 256 + tid] = gelu_t(v3);
    }
    __syncthreads();

    // ---- Phase B: layer2 GEMM (M=256, N=64, K=64), 8x8 tile per thread ----
    int jg = tid & 7;        // j group: cols jg*8 .. jg*8+7
    int rg = tid >> 3;       // row group: rows rg*8 .. rg*8+7

    u64 acc[8][4];
    #pragma unroll
    for (int c = 0; c < 8; ++c)
        #pragma unroll
        for (int p = 0; p < 4; ++p) acc[c][p] = 0ULL;

    const float* hbase = hs + rg * 8;
    const float* wbase = sW2 + jg * 8;
    #pragma unroll 4
    for (int k = 0; k < 64; ++k) {
        float4 ha = *(const float4*)(hbase + k * 256);
        float4 hb = *(const float4*)(hbase + k * 256 + 4);
        ulonglong2 wa = *(const ulonglong2*)(wbase + k * 64);
        ulonglong2 wb = *(const ulonglong2*)(wbase + k * 64 + 4);
        u64 hd;
        hd = pk2(ha.x, ha.x);
        acc[0][0] = ffma2(hd, wa.x, acc[0][0]); acc[0][1] = ffma2(hd, wa.y, acc[0][1]);
        acc[0][2] = ffma2(hd, wb.x, acc[0][2]); acc[0][3] = ffma2(hd, wb.y, acc[0][3]);
        hd = pk2(ha.y, ha.y);
        acc[1][0] = ffma2(hd, wa.x, acc[1][0]); acc[1][1] = ffma2(hd, wa.y, acc[1][1]);
        acc[1][2] = ffma2(hd, wb.x, acc[1][2]); acc[1][3] = ffma2(hd, wb.y, acc[1][3]);
        hd = pk2(ha.z, ha.z);
        acc[2][0] = ffma2(hd, wa.x, acc[2][0]); acc[2][1] = ffma2(hd, wa.y, acc[2][1]);
        acc[2][2] = ffma2(hd, wb.x, acc[2][2]); acc[2][3] = ffma2(hd, wb.y, acc[2][3]);
        hd = pk2(ha.w, ha.w);
        acc[3][0] = ffma2(hd, wa.x, acc[3][0]); acc[3][1] = ffma2(hd, wa.y, acc[3][1]);
        acc[3][2] = ffma2(hd, wb.x, acc[3][2]); acc[3][3] = ffma2(hd, wb.y, acc[3][3]);
        hd = pk2(hb.x, hb.x);
        acc[4][0] = ffma2(hd, wa.x, acc[4][0]); acc[4][1] = ffma2(hd, wa.y, acc[4][1]);
        acc[4][2] = ffma2(hd, wb.x, acc[4][2]); acc[4][3] = ffma2(hd, wb.y, acc[4][3]);
        hd = pk2(hb.y, hb.y);
        acc[5][0] = ffma2(hd, wa.x, acc[5][0]); acc[5][1] = ffma2(hd, wa.y, acc[5][1]);
        acc[5][2] = ffma2(hd, wb.x, acc[5][2]); acc[5][3] = ffma2(hd, wb.y, acc[5][3]);
        hd = pk2(hb.z, hb.z);
        acc[6][0] = ffma2(hd, wa.x, acc[6][0]); acc[6][1] = ffma2(hd, wa.y, acc[6][1]);
        acc[6][2] = ffma2(hd, wb.x, acc[6][2]); acc[6][3] = ffma2(hd, wb.y, acc[6][3]);
        hd = pk2(hb.w, hb.w);
        acc[7][0] = ffma2(hd, wa.x, acc[7][0]); acc[7][1] = ffma2(hd, wa.y, acc[7][1]);
        acc[7][2] = ffma2(hd, wb.x, acc[7][2]); acc[7][3] = ffma2(hd, wb.y, acc[7][3]);
    }

    // epilogue: gelu + layer3 partials, butterfly-reduce over 8 j-lanes
    int j0 = jg * 8;
    float myLg0 = 0.f, myLg1 = 0.f;
    #pragma unroll
    for (int c = 0; c < 8; ++c) {
        float lg0 = 0.f, lg1 = 0.f;
        #pragma unroll
        for (int p = 0; p < 4; ++p) {
            float a0, a1;
            upk2(acc[c][p], a0, a1);
            int j = j0 + 2 * p;
            float h2a = gelu_t(a0 + sB2[j]);
            float h2b = gelu_t(a1 + sB2[j + 1]);
            lg0 = fmaf(h2a, sW3[2 * j],     lg0); lg1 = fmaf(h2a, sW3[2 * j + 1], lg1);
            lg0 = fmaf(h2b, sW3[2 * j + 2], lg0); lg1 = fmaf(h2b, sW3[2 * j + 3], lg1);
        }
        lg0 += __shfl_xor_sync(0xffffffffu, lg0, 4);
        lg1 += __shfl_xor_sync(0xffffffffu, lg1, 4);
        lg0 += __shfl_xor_sync(0xffffffffu, lg0, 2);
        lg1 += __shfl_xor_sync(0xffffffffu, lg1, 2);
        lg0 += __shfl_xor_sync(0xffffffffu, lg0, 1);
        lg1 += __shfl_xor_sync(0xffffffffu, lg1, 1);
        if (jg == c) { myLg0 = lg0; myLg1 = lg1; }
    }

    // lane jg handles row rg*8 + jg -> coalesced across warp
    int row = rg * 8 + jg;
    int og  = blockIdx.x * 256 + row;
    float lg0 = myLg0 + sCst[1];
    float lg1 = myLg1 + sCst[2];
    float mx = fmaxf(lg0, lg1);
    float e0 = __expf(lg0 - mx), e1 = __expf(lg1 - mx);
    float inv = __fdividef(1.0f, e0 + e1);
    float g0 = e0 * inv, g1 = e1 * inv;

    float xgr = sXg[row], xfr = sXf[row], mmr = sMm[row], xir = sXi[row];
    float imputed  = fmaf(g0, xgr, g1 * xfr);
    float complete = (mmr != 0.f) ? imputed : xir;

    out_imp[og]  = imputed;
    out_comp[og] = complete;
    float2 gv; gv.x = g0; gv.y = g1;
    *(float2*)(out_gate + (size_t)og * 2) = gv;
}

// ---------------------------------------------------------------------------
extern "C" void kernel_launch(void* const* d_in, const int* in_sizes, int n_in,
                              void* d_out, int out_size)
{
    const float* x     = (const float*)d_in[0];
    const float* mask  = (const float*)d_in[1];
    const int*   rid   = (const int*)  d_in[2];
    const float* emb   = (const float*)d_in[3];
    const float* gcw1  = (const float*)d_in[4];
    const float* gcb1  = (const float*)d_in[5];
    const float* gcw2  = (const float*)d_in[6];
    const float* gcb2  = (const float*)d_in[7];
    const float* fre   = (const float*)d_in[8];
    const float* fim   = (const float*)d_in[9];
    const float* rtab  = (const float*)d_in[10];
    const float* gw1   = (const float*)d_in[11];
    const float* gb1   = (const float*)d_in[12];
    const float* gw2   = (const float*)d_in[13];
    const float* gb2   = (const float*)d_in[14];
    const float* gw3   = (const float*)d_in[15];
    const float* gb3   = (const float*)d_in[16];
    float* out = (float*)d_out;

    cudaFuncSetAttribute(fused_kernel, cudaFuncAttributeMaxDynamicSharedMemorySize, SMEM_BYTES);

    fill_kernel<<<B_, 1024>>>(x, mask, out + SEED_OFF);
    adj_kernel<<<1, 64>>>(emb, rid, rtab, gw1, gb1, out + ADJ_OFF);
    fft_kernel<<<B_ * N_ / 2, 256>>>(out + SEED_OFF, fre, fim, out + FREQ_OFF);
    fused_kernel<<<B_ * T_ * N_ / 256, 256, SMEM_BYTES>>>(
        out + SEED_OFF, mask, x, out + FREQ_OFF,
        gw1, gw2, gb2, gw3, gb3,
        gcw1, gcb1, gcw2, gcb2,
        out + GCN_OFF, out + IMP_OFF, out + COMP_OFF, out + GATE_OFF);
}

// round 3
// speedup vs baseline: 1.2800x; 1.1614x over previous
#include <cuda_runtime.h>
#include <cuda_bf16.h>
#include <math.h>

#define B_ 16
#define T_ 2048
#define N_ 64

// Output layout (flattened tuple in order)
#define SEED_OFF 0
#define GCN_OFF  2097152
#define FREQ_OFF 4194304
#define IMP_OFF  6291456
#define COMP_OFF 8388608
#define GATE_OFF 10485760
#define ADJ_OFF  14680064

typedef unsigned long long u64;

// Scratch (static device arrays: allowed)
__device__ float  g_adj[N_ * N_];
__device__ float2 g_preb1p[32 * N_];
// fill scan scratch: [b][chunk][n], 16*64*64 = 65536
__device__ float  g_first[65536], g_last[65536];
__device__ unsigned char g_has[65536];
__device__ float  g_pref[65536], g_suf[65536];
__device__ unsigned char g_prefh[65536], g_sufh[65536];

// ---- packed f32x2 helpers ---------------------------------------------------
__device__ __forceinline__ u64 pk2(float lo, float hi) {
    u64 r; asm("mov.b64 %0, {%1, %2};" : "=l"(r) : "f"(lo), "f"(hi)); return r;
}
__device__ __forceinline__ void upk2(u64 v, float& lo, float& hi) {
    asm("mov.b64 {%0, %1}, %2;" : "=f"(lo), "=f"(hi) : "l"(v));
}
__device__ __forceinline__ u64 ffma2(u64 a, u64 b, u64 c) {
    u64 d; asm("fma.rn.f32x2 %0, %1, %2, %3;" : "=l"(d) : "l"(a), "l"(b), "l"(c)); return d;
}

__device__ __forceinline__ float gelu_t(float x) {
    float x2 = x * x;
    float b = x * fmaf(0.0713548162726f, x2, 1.59576912161f);
    float e = __expf(b);
    float r = __fdividef(2.0f, e + 1.0f);
    float t = 1.0f - r;
    float hx = 0.5f * x;
    return fmaf(hx, t, hx);
}

// ---------------------------------------------------------------------------
// Fill stage 1: 32-step chunk summaries. grid 256 x 256 threads.
// thread -> (b, c, n): n fastest. idx layout si = b*4096 + c*64 + n.
// ---------------------------------------------------------------------------
__global__ void __launch_bounds__(256) fill_sum_kernel(
    const float* __restrict__ x, const float* __restrict__ mask)
{
    int g = blockIdx.x * 256 + threadIdx.x;
    int n = g & 63;
    int c = (g >> 6) & 63;
    int b = g >> 12;
    int base = ((b * T_) + c * 32) * N_ + n;
    float first = 0.f, last = 0.f; bool has = false;
    #pragma unroll
    for (int t = 0; t < 32; ++t) {
        int idx = base + t * N_;
        float v = x[idx];
        bool obs = (mask[idx] == 0.f);
        if (obs) { if (!has) first = v; last = v; has = true; }
    }
    g_first[g] = first; g_last[g] = last; g_has[g] = (unsigned char)has;
}

// ---------------------------------------------------------------------------
// Fill stage 2: per (b,n) scan over 64 chunks. 1024 threads total.
// ---------------------------------------------------------------------------
__global__ void __launch_bounds__(256) fill_scan_kernel()
{
    int g = blockIdx.x * 256 + threadIdx.x;   // 0..1023
    int b = g >> 6, n = g & 63;
    int base = b * 4096 + n;
    float pv = 0.f; bool ph = false;
    #pragma unroll 8
    for (int c = 0; c < 64; ++c) {
        int i = base + c * 64;
        g_pref[i] = pv; g_prefh[i] = (unsigned char)ph;
        if (g_has[i]) { pv = g_last[i]; ph = true; }
    }
    float sv = 0.f; bool sh = false;
    #pragma unroll 8
    for (int c = 63; c >= 0; --c) {
        int i = base + c * 64;
        g_suf[i] = sv; g_sufh[i] = (unsigned char)sh;
        if (g_has[i]) { sv = g_first[i]; sh = true; }
    }
}

// ---------------------------------------------------------------------------
// Fill stage 3: fwd+bwd fill resolved in registers, write seed.
// ---------------------------------------------------------------------------
__global__ void __launch_bounds__(256) fill_out_kernel(
    const float* __restrict__ x, const float* __restrict__ mask,
    float* __restrict__ seed)
{
    int g = blockIdx.x * 256 + threadIdx.x;
    int n = g & 63;
    int c = (g >> 6) & 63;
    int b = g >> 12;
    int base = ((b * T_) + c * 32) * N_ + n;

    float fv = g_pref[g]; bool fh = (bool)g_prefh[g];
    float vals[32];
    unsigned obsm = 0u, fam = 0u;
    #pragma unroll
    for (int t = 0; t < 32; ++t) {
        int idx = base + t * N_;
        float v = x[idx];
        bool obs = (mask[idx] == 0.f);
        if (obs) { fv = v; fh = true; obsm |= (1u << t); }
        vals[t] = fv;
        if (fh) fam |= (1u << t);
    }
    float bv = g_suf[g]; bool bh = (bool)g_sufh[g];
    #pragma unroll
    for (int t = 31; t >= 0; --t) {
        bool obs = (obsm >> t) & 1u;
        bool fa  = (fam  >> t) & 1u;
        float v = vals[t];
        if (obs) { bv = v; bh = true; }
        float out;
        if (obs)            out = v;
        else if (fa && bh)  out = 0.5f * (v + bv);
        else if (fa)        out = v;
        else if (bh)        out = bv;
        else                out = 0.f;
        seed[base + t * N_] = out;
    }
}

// ---------------------------------------------------------------------------
// Kernel 2: adjacency + rate-embed pre-bias (paired layout)
// ---------------------------------------------------------------------------
__global__ void __launch_bounds__(64) adj_kernel(
    const float* __restrict__ emb, const int* __restrict__ rate_id,
    const float* __restrict__ rate_table, const float* __restrict__ gw1,
    const float* __restrict__ gb1, float* __restrict__ out_adj)
{
    __shared__ float sE[64 * 32];
    int tid = threadIdx.x;
    for (int i = tid; i < 64 * 32; i += 64) sE[i] = emb[i];
    __syncthreads();

    float sc[64];
    float mx = -1e30f;
    #pragma unroll
    for (int m = 0; m < 64; ++m) {
        float d = 0.f;
        #pragma unroll
        for (int h = 0; h < 32; ++h) d = fmaf(sE[tid * 32 + h], sE[m * 32 + h], d);
        d = fmaxf(d, 0.f);
        sc[m] = d; mx = fmaxf(mx, d);
    }
    float sum = 0.f;
    #pragma unroll
    for (int m = 0; m < 64; ++m) { float e = __expf(sc[m] - mx); sc[m] = e; sum += e; }
    float inv = 1.0f / sum;
    #pragma unroll
    for (int m = 0; m < 64; ++m) {
        float a = sc[m] * inv;
        g_adj[tid * 64 + m] = a;
        out_adj[tid * 64 + m] = a;
    }
    int rid = rate_id[tid];
    for (int j2 = 0; j2 < 32; ++j2) {
        float v0 = gb1[2 * j2], v1 = gb1[2 * j2 + 1];
        #pragma unroll
        for (int e = 0; e < 16; ++e) {
            float rt = rate_table[rid * 16 + e];
            v0 = fmaf(rt, gw1[(6 + e) * 64 + 2 * j2], v0);
            v1 = fmaf(rt, gw1[(6 + e) * 64 + 2 * j2 + 1], v1);
        }
        g_preb1p[j2 * 64 + tid] = make_float2(v0, v1);
    }
}

// ---------------------------------------------------------------------------
// Kernel 3: packed-pair radix-2 FFT filter
// ---------------------------------------------------------------------------
__global__ void __launch_bounds__(256) fft_kernel(
    const float* __restrict__ seed, const float* __restrict__ fre,
    const float* __restrict__ fim, float* __restrict__ xfreq)
{
    __shared__ float re[2048], im[2048], twr[1024], twi[1024];
    int tid = threadIdx.x;
    int b = blockIdx.x >> 5;
    int p = blockIdx.x & 31;
    int n0 = p * 2;
    const float* src = seed + (size_t)b * T_ * N_ + n0;

    for (int j = tid; j < 1024; j += 256) {
        float s, c;
        sincosf(-6.28318530717958647692f * (float)j * (1.0f / 2048.0f), &s, &c);
        twr[j] = c; twi[j] = s;
    }
    for (int t = tid; t < 2048; t += 256) {
        float2 v = *(const float2*)(src + (size_t)t * N_);
        re[t] = v.x; im[t] = v.y;
    }

    for (int s = 10; s >= 0; --s) {
        int half = 1 << s;
        __syncthreads();
        for (int bi = tid; bi < 1024; bi += 256) {
            int j = bi & (half - 1);
            int i1 = ((bi >> s) << (s + 1)) | j;
            int i2 = i1 + half;
            int tj = j << (10 - s);
            float wr = twr[tj], wi = twi[tj];
            float ar = re[i1], ai = im[i1], br = re[i2], b2 = im[i2];
            re[i1] = ar + br; im[i1] = ai + b2;
            float dr = ar - br, di = ai - b2;
            re[i2] = dr * wr - di * wi;
            im[i2] = dr * wi + di * wr;
        }
    }
    __syncthreads();

    for (int k = tid; k <= 1024; k += 256) {
        int km = (2048 - k) & 2047;
        int pk = __brev(k) >> 21;
        int pm = __brev(km) >> 21;
        float zr = re[pk], zi = im[pk];
        float yr = re[pm], yi = im[pm];
        float x1r = 0.5f * (zr + yr), x1i = 0.5f * (zi - yi);
        float x2r = 0.5f * (zi + yi), x2i = 0.5f * (yr - zr);
        float h1r = fre[(size_t)k * N_ + n0],     h1i = fim[(size_t)k * N_ + n0];
        float h2r = fre[(size_t)k * N_ + n0 + 1], h2i = fim[(size_t)k * N_ + n0 + 1];
        float y1r = x1r * h1r - x1i * h1i, y1i = x1r * h1i + x1i * h1r;
        float y2r = x2r * h2r - x2i * h2i, y2i = x2r * h2i + x2i * h2r;
        if (k == 0 || k == 1024) { y1i = 0.f; y2i = 0.f; }
        re[pk] = y1r - y2i; im[pk] = y1i + y2r;
        if (k > 0 && k < 1024) { re[pm] = y1r + y2i; im[pm] = y2r - y1i; }
    }

    for (int s = 0; s <= 10; ++s) {
        int half = 1 << s;
        __syncthreads();
        for (int bi = tid; bi < 1024; bi += 256) {
            int j = bi & (half - 1);
            int i1 = ((bi >> s) << (s + 1)) | j;
            int i2 = i1 + half;
            int tj = j << (10 - s);
            float wr = twr[tj], wi = -twi[tj];
            float br = re[i2], b2 = im[i2];
            float tr = br * wr - b2 * wi, ti = br * wi + b2 * wr;
            float ar = re[i1], ai = im[i1];
            re[i1] = ar + tr; im[i1] = ai + ti;
            re[i2] = ar - tr; im[i2] = ai - ti;
        }
    }
    __syncthreads();

    float* dst = xfreq + (size_t)b * T_ * N_ + n0;
    const float scl = 1.0f / 2048.0f;
    for (int t = tid; t < 2048; t += 256) {
        float2 v; v.x = re[t] * scl; v.y = im[t] * scl;
        *(float2*)(dst + (size_t)t * N_) = v;
    }
}

// ---------------------------------------------------------------------------
// Kernel 4 v3: 512 threads/CTA (16 warps/SM), 512 elements/CTA.
// Phase A: per-element feats + layer1 -> hs[64][512].
// Phase B: 64 rowgrp x 8 jgrp, 8x8 FFMA2 tile per thread.
// ---------------------------------------------------------------------------
#define FTH 512
#define SMEM_BYTES 177056

__global__ void __launch_bounds__(FTH, 1) fused_kernel(
    const float* __restrict__ seed, const float* __restrict__ mask,
    const float* __restrict__ xin, const float* __restrict__ xfreq,
    const float* __restrict__ gw1, const float* __restrict__ gw2,
    const float* __restrict__ gb2, const float* __restrict__ gw3,
    const float* __restrict__ gb3,
    const float* __restrict__ gcw1, const float* __restrict__ gcb1,
    const float* __restrict__ gcw2, const float* __restrict__ gcb2,
    float* __restrict__ out_gcn, float* __restrict__ out_imp,
    float* __restrict__ out_comp, float* __restrict__ out_gate)
{
    extern __shared__ float sm[];
    float* hs   = sm;                // [64][512]  131072B
    float* sW2  = hs  + 64 * FTH;    // [64][64]
    float* sA   = sW2 + 64 * 64;     // [64][65]
    float* sW1  = sA  + 64 * 65;     // [6][64]
    float* sW3  = sW1 + 384;
    float* sB2  = sW3 + 128;
    float* sGc  = sB2 + 64;
    float* sCst = sGc + 96;
    float* sPm  = sCst + 4;          // [8][64]
    float* sXg  = sPm + FTH;
    float* sXf  = sXg + FTH;
    float* sMm  = sXf + FTH;
    float* sXi  = sMm + FTH;

    int tid = threadIdx.x;

    for (int i = tid; i < 4096; i += FTH) sW2[i] = gw2[i];
    for (int i = tid; i < 4096; i += FTH) sA[(i >> 6) * 65 + (i & 63)] = g_adj[i];
    if (tid < 384) sW1[tid] = gw1[tid];
    if (tid < 128) sW3[tid] = gw3[tid];
    if (tid < 64) sB2[tid] = gb2[tid];
    if (tid < 32) { sGc[tid] = gcw1[tid]; sGc[32 + tid] = gcb1[tid]; sGc[64 + tid] = gcw2[tid]; }
    if (tid == 0) { sCst[0] = gcb2[0]; sCst[1] = gb3[0]; sCst[2] = gb3[1]; }

    int n = tid & 63;
    int r = tid >> 6;                       // 0..7
    int gidx = blockIdx.x * FTH + tid;

    float s  = seed[gidx];
    float mm = mask[gidx];
    float xf = xfreq[gidx];
    float xi = xin[gidx];
    __syncthreads();

    // phi(s)
    float pv = 0.f;
    #pragma unroll
    for (int h = 0; h < 32; ++h)
        pv = fmaf(sGc[64 + h], gelu_t(fmaf(s, sGc[h], sGc[32 + h])), pv);
    sPm[r * 64 + n] = pv;
    __syncthreads();

    // x_gcn
    float xg = sCst[0];
    #pragma unroll 8
    for (int m = 0; m < 64; ++m)
        xg = fmaf(sA[n * 65 + m], sPm[r * 64 + m], xg);

    sXg[tid] = xg; sXf[tid] = xf; sMm[tid] = mm; sXi[tid] = xi;
    out_gcn[gidx] = xg;

    u64 u0 = pk2(s, s), u1 = pk2(mm, mm), u2 = pk2(xg, xg);
    u64 u3 = pk2(xf, xf), u4 = pk2(xg - s, xg - s), u5 = pk2(xf - s, xf - s);

    const float4* W1v = (const float4*)sW1;
    #pragma unroll
    for (int jq = 0; jq < 16; ++jq) {
        float2 pA = g_preb1p[(2 * jq) * 64 + n];
        float2 pB = g_preb1p[(2 * jq + 1) * 64 + n];
        u64 a0 = pk2(pA.x, pA.y);
        u64 a1 = pk2(pB.x, pB.y);
        float4 w;
        u64 wp;
        w = W1v[0 * 16 + jq]; wp = pk2(w.x, w.y); a0 = ffma2(u0, wp, a0); wp = pk2(w.z, w.w); a1 = ffma2(u0, wp, a1);
        w = W1v[1 * 16 + jq]; wp = pk2(w.x, w.y); a0 = ffma2(u1, wp, a0); wp = pk2(w.z, w.w); a1 = ffma2(u1, wp, a1);
        w = W1v[2 * 16 + jq]; wp = pk2(w.x, w.y); a0 = ffma2(u2, wp, a0); wp = pk2(w.z, w.w); a1 = ffma2(u2, wp, a1);
        w = W1v[3 * 16 + jq]; wp = pk2(w.x, w.y); a0 = ffma2(u3, wp, a0); wp = pk2(w.z, w.w); a1 = ffma2(u3, wp, a1);
        w = W1v[4 * 16 + jq]; wp = pk2(w.x, w.y); a0 = ffma2(u4, wp, a0); wp = pk2(w.z, w.w); a1 = ffma2(u4, wp, a1);
        w = W1v[5 * 16 + jq]; wp = pk2(w.x, w.y); a0 = ffma2(u5, wp, a0); wp = pk2(w.z, w.w); a1 = ffma2(u5, wp, a1);
        float v0, v1, v2, v3;
        upk2(a0, v0, v1); upk2(a1, v2, v3);
        hs[(4 * jq + 0) * FTH + tid] = gelu_t(v0);
        hs[(4 * jq + 1) * FTH + tid] = gelu_t(v1);
        hs[(4 * jq + 2) * FTH + tid] = gelu_t(v2);
        hs[(4 * jq + 3) * FTH + tid] = gelu_t(v3);
    }
    __syncthreads();

    // ---- Phase B ----
    int jg = tid & 7;
    int rg = tid >> 3;   // 0..63

    u64 acc[8][4];
    #pragma unroll
    for (int c = 0; c < 8; ++c)
        #pragma unroll
        for (int p = 0; p < 4; ++p) acc[c][p] = 0ULL;

    const float* hbase = hs + rg * 8;
    const float* wbase = sW2 + jg * 8;
    #pragma unroll 4
    for (int k = 0; k < 64; ++k) {
        float4 ha = *(const float4*)(hbase + k * FTH);
        float4 hb = *(const float4*)(hbase + k * FTH + 4);
        ulonglong2 wa = *(const ulonglong2*)(wbase + k * 64);
        ulonglong2 wb = *(const ulonglong2*)(wbase + k * 64 + 4);
        u64 hd;
        hd = pk2(ha.x, ha.x);
        acc[0][0] = ffma2(hd, wa.x, acc[0][0]); acc[0][1] = ffma2(hd, wa.y, acc[0][1]);
        acc[0][2] = ffma2(hd, wb.x, acc[0][2]); acc[0][3] = ffma2(hd, wb.y, acc[0][3]);
        hd = pk2(ha.y, ha.y);
        acc[1][0] = ffma2(hd, wa.x, acc[1][0]); acc[1][1] = ffma2(hd, wa.y, acc[1][1]);
        acc[1][2] = ffma2(hd, wb.x, acc[1][2]); acc[1][3] = ffma2(hd, wb.y, acc[1][3]);
        hd = pk2(ha.z, ha.z);
        acc[2][0] = ffma2(hd, wa.x, acc[2][0]); acc[2][1] = ffma2(hd, wa.y, acc[2][1]);
        acc[2][2] = ffma2(hd, wb.x, acc[2][2]); acc[2][3] = ffma2(hd, wb.y, acc[2][3]);
        hd = pk2(ha.w, ha.w);
        acc[3][0] = ffma2(hd, wa.x, acc[3][0]); acc[3][1] = ffma2(hd, wa.y, acc[3][1]);
        acc[3][2] = ffma2(hd, wb.x, acc[3][2]); acc[3][3] = ffma2(hd, wb.y, acc[3][3]);
        hd = pk2(hb.x, hb.x);
        acc[4][0] = ffma2(hd, wa.x, acc[4][0]); acc[4][1] = ffma2(hd, wa.y, acc[4][1]);
        acc[4][2] = ffma2(hd, wb.x, acc[4][2]); acc[4][3] = ffma2(hd, wb.y, acc[4][3]);
        hd = pk2(hb.y, hb.y);
        acc[5][0] = ffma2(hd, wa.x, acc[5][0]); acc[5][1] = ffma2(hd, wa.y, acc[5][1]);
        acc[5][2] = ffma2(hd, wb.x, acc[5][2]); acc[5][3] = ffma2(hd, wb.y, acc[5][3]);
        hd = pk2(hb.z, hb.z);
        acc[6][0] = ffma2(hd, wa.x, acc[6][0]); acc[6][1] = ffma2(hd, wa.y, acc[6][1]);
        acc[6][2] = ffma2(hd, wb.x, acc[6][2]); acc[6][3] = ffma2(hd, wb.y, acc[6][3]);
        hd = pk2(hb.w, hb.w);
        acc[7][0] = ffma2(hd, wa.x, acc[7][0]); acc[7][1] = ffma2(hd, wa.y, acc[7][1]);
        acc[7][2] = ffma2(hd, wb.x, acc[7][2]); acc[7][3] = ffma2(hd, wb.y, acc[7][3]);
    }

    int j0 = jg * 8;
    float myLg0 = 0.f, myLg1 = 0.f;
    #pragma unroll
    for (int c = 0; c < 8; ++c) {
        float lg0 = 0.f, lg1 = 0.f;
        #pragma unroll
        for (int p = 0; p < 4; ++p) {
            float a0, a1;
            upk2(acc[c][p], a0, a1);
            int j = j0 + 2 * p;
            float h2a = gelu_t(a0 + sB2[j]);
            float h2b = gelu_t(a1 + sB2[j + 1]);
            lg0 = fmaf(h2a, sW3[2 * j],     lg0); lg1 = fmaf(h2a, sW3[2 * j + 1], lg1);
            lg0 = fmaf(h2b, sW3[2 * j + 2], lg0); lg1 = fmaf(h2b, sW3[2 * j + 3], lg1);
        }
        lg0 += __shfl_xor_sync(0xffffffffu, lg0, 4);
        lg1 += __shfl_xor_sync(0xffffffffu, lg1, 4);
        lg0 += __shfl_xor_sync(0xffffffffu, lg0, 2);
        lg1 += __shfl_xor_sync(0xffffffffu, lg1, 2);
        lg0 += __shfl_xor_sync(0xffffffffu, lg0, 1);
        lg1 += __shfl_xor_sync(0xffffffffu, lg1, 1);
        if (jg == c) { myLg0 = lg0; myLg1 = lg1; }
    }

    int row = rg * 8 + jg;
    int og  = blockIdx.x * FTH + row;
    float lg0 = myLg0 + sCst[1];
    float lg1 = myLg1 + sCst[2];
    float mx = fmaxf(lg0, lg1);
    float e0 = __expf(lg0 - mx), e1 = __expf(lg1 - mx);
    float inv = __fdividef(1.0f, e0 + e1);
    float g0 = e0 * inv, g1 = e1 * inv;

    float xgr = sXg[row], xfr = sXf[row], mmr = sMm[row], xir = sXi[row];
    float imputed  = fmaf(g0, xgr, g1 * xfr);
    float complete = (mmr != 0.f) ? imputed : xir;

    out_imp[og]  = imputed;
    out_comp[og] = complete;
    float2 gv; gv.x = g0; gv.y = g1;
    *(float2*)(out_gate + (size_t)og * 2) = gv;
}

// ---------------------------------------------------------------------------
extern "C" void kernel_launch(void* const* d_in, const int* in_sizes, int n_in,
                              void* d_out, int out_size)
{
    const float* x     = (const float*)d_in[0];
    const float* mask  = (const float*)d_in[1];
    const int*   rid   = (const int*)  d_in[2];
    const float* emb   = (const float*)d_in[3];
    const float* gcw1  = (const float*)d_in[4];
    const float* gcb1  = (const float*)d_in[5];
    const float* gcw2  = (const float*)d_in[6];
    const float* gcb2  = (const float*)d_in[7];
    const float* fre   = (const float*)d_in[8];
    const float* fim   = (const float*)d_in[9];
    const float* rtab  = (const float*)d_in[10];
    const float* gw1   = (const float*)d_in[11];
    const float* gb1   = (const float*)d_in[12];
    const float* gw2   = (const float*)d_in[13];
    const float* gb2   = (const float*)d_in[14];
    const float* gw3   = (const float*)d_in[15];
    const float* gb3   = (const float*)d_in[16];
    float* out = (float*)d_out;

    cudaFuncSetAttribute(fused_kernel, cudaFuncAttributeMaxDynamicSharedMemorySize, SMEM_BYTES);

    adj_kernel<<<1, 64>>>(emb, rid, rtab, gw1, gb1, out + ADJ_OFF);
    fill_sum_kernel<<<256, 256>>>(x, mask);
    fill_scan_kernel<<<4, 256>>>();
    fill_out_kernel<<<256, 256>>>(x, mask, out + SEED_OFF);
    fft_kernel<<<B_ * N_ / 2, 256>>>(out + SEED_OFF, fre, fim, out + FREQ_OFF);
    fused_kernel<<<B_ * T_ * N_ / FTH, FTH, SMEM_BYTES>>>(
        out + SEED_OFF, mask, x, out + FREQ_OFF,
        gw1, gw2, gb2, gw3, gb3,
        gcw1, gcb1, gcw2, gcb2,
        out + GCN_OFF, out + IMP_OFF, out + COMP_OFF, out + GATE_OFF);
}

// round 4
// speedup vs baseline: 1.5300x; 1.1953x over previous
#include <cuda_runtime.h>
#include <cuda_bf16.h>
#include <math.h>

#define B_ 16
#define T_ 2048
#define N_ 64

// Output layout (flattened tuple in order)
#define SEED_OFF 0
#define GCN_OFF  2097152
#define FREQ_OFF 4194304
#define IMP_OFF  6291456
#define COMP_OFF 8388608
#define GATE_OFF 10485760
#define ADJ_OFF  14680064

typedef unsigned long long u64;

// Scratch (static device arrays: allowed)
__device__ float  g_adj[N_ * N_];
__device__ float2 g_preb1p[32 * N_];
// fill scan scratch: [b][chunk][n], 16*64*64 = 65536
__device__ float  g_first[65536], g_last[65536];
__device__ unsigned char g_has[65536];
__device__ float  g_pref[65536], g_suf[65536];
__device__ unsigned char g_prefh[65536], g_sufh[65536];

// ---- packed f32x2 helpers ---------------------------------------------------
__device__ __forceinline__ u64 pk2(float lo, float hi) {
    u64 r; asm("mov.b64 %0, {%1, %2};" : "=l"(r) : "f"(lo), "f"(hi)); return r;
}
__device__ __forceinline__ void upk2(u64 v, float& lo, float& hi) {
    asm("mov.b64 {%0, %1}, %2;" : "=f"(lo), "=f"(hi) : "l"(v));
}
__device__ __forceinline__ u64 ffma2(u64 a, u64 b, u64 c) {
    u64 d; asm("fma.rn.f32x2 %0, %1, %2, %3;" : "=l"(d) : "l"(a), "l"(b), "l"(c)); return d;
}

// tanh-approx gelu via MUFU tanh (sm_75+): ~4 fma + 1 MUFU
__device__ __forceinline__ float gelu_t(float x) {
    float x2 = x * x;
    float inner = fmaf(x2, 0.035677408136f, 0.7978845608028654f);
    float b = x * inner;
    float t;
    asm("tanh.approx.f32 %0, %1;" : "=f"(t) : "f"(b));
    float hx = 0.5f * x;
    return fmaf(hx, t, hx);
}

// ---------------------------------------------------------------------------
// Fill stage 1: 32-step chunk summaries. grid 256 x 256 threads.
// ---------------------------------------------------------------------------
__global__ void __launch_bounds__(256) fill_sum_kernel(
    const float* __restrict__ x, const float* __restrict__ mask)
{
    int g = blockIdx.x * 256 + threadIdx.x;
    int n = g & 63;
    int c = (g >> 6) & 63;
    int b = g >> 12;
    int base = ((b * T_) + c * 32) * N_ + n;
    float first = 0.f, last = 0.f; bool has = false;
    #pragma unroll
    for (int t = 0; t < 32; ++t) {
        int idx = base + t * N_;
        float v = x[idx];
        bool obs = (mask[idx] == 0.f);
        if (obs) { if (!has) first = v; last = v; has = true; }
    }
    g_first[g] = first; g_last[g] = last; g_has[g] = (unsigned char)has;
}

// ---------------------------------------------------------------------------
// Fill stage 2: per (b,n) scan over 64 chunks.
// ---------------------------------------------------------------------------
__global__ void __launch_bounds__(256) fill_scan_kernel()
{
    int g = blockIdx.x * 256 + threadIdx.x;   // 0..1023
    int b = g >> 6, n = g & 63;
    int base = b * 4096 + n;
    float pv = 0.f; bool ph = false;
    #pragma unroll 8
    for (int c = 0; c < 64; ++c) {
        int i = base + c * 64;
        g_pref[i] = pv; g_prefh[i] = (unsigned char)ph;
        if (g_has[i]) { pv = g_last[i]; ph = true; }
    }
    float sv = 0.f; bool sh = false;
    #pragma unroll 8
    for (int c = 63; c >= 0; --c) {
        int i = base + c * 64;
        g_suf[i] = sv; g_sufh[i] = (unsigned char)sh;
        if (g_has[i]) { sv = g_first[i]; sh = true; }
    }
}

// ---------------------------------------------------------------------------
// Fill stage 3: fwd+bwd fill resolved in registers, write seed.
// ---------------------------------------------------------------------------
__global__ void __launch_bounds__(256) fill_out_kernel(
    const float* __restrict__ x, const float* __restrict__ mask,
    float* __restrict__ seed)
{
    int g = blockIdx.x * 256 + threadIdx.x;
    int n = g & 63;
    int c = (g >> 6) & 63;
    int b = g >> 12;
    int base = ((b * T_) + c * 32) * N_ + n;

    float fv = g_pref[g]; bool fh = (bool)g_prefh[g];
    float vals[32];
    unsigned obsm = 0u, fam = 0u;
    #pragma unroll
    for (int t = 0; t < 32; ++t) {
        int idx = base + t * N_;
        float v = x[idx];
        bool obs = (mask[idx] == 0.f);
        if (obs) { fv = v; fh = true; obsm |= (1u << t); }
        vals[t] = fv;
        if (fh) fam |= (1u << t);
    }
    float bv = g_suf[g]; bool bh = (bool)g_sufh[g];
    #pragma unroll
    for (int t = 31; t >= 0; --t) {
        bool obs = (obsm >> t) & 1u;
        bool fa  = (fam  >> t) & 1u;
        float v = vals[t];
        if (obs) { bv = v; bh = true; }
        float out;
        if (obs)            out = v;
        else if (fa && bh)  out = 0.5f * (v + bv);
        else if (fa)        out = v;
        else if (bh)        out = bv;
        else                out = 0.f;
        seed[base + t * N_] = out;
    }
}

// ---------------------------------------------------------------------------
// Kernel 2: adjacency + rate-embed pre-bias (paired layout)
// ---------------------------------------------------------------------------
__global__ void __launch_bounds__(64) adj_kernel(
    const float* __restrict__ emb, const int* __restrict__ rate_id,
    const float* __restrict__ rate_table, const float* __restrict__ gw1,
    const float* __restrict__ gb1, float* __restrict__ out_adj)
{
    __shared__ float sE[64 * 32];
    int tid = threadIdx.x;
    for (int i = tid; i < 64 * 32; i += 64) sE[i] = emb[i];
    __syncthreads();

    float sc[64];
    float mx = -1e30f;
    #pragma unroll
    for (int m = 0; m < 64; ++m) {
        float d = 0.f;
        #pragma unroll
        for (int h = 0; h < 32; ++h) d = fmaf(sE[tid * 32 + h], sE[m * 32 + h], d);
        d = fmaxf(d, 0.f);
        sc[m] = d; mx = fmaxf(mx, d);
    }
    float sum = 0.f;
    #pragma unroll
    for (int m = 0; m < 64; ++m) { float e = __expf(sc[m] - mx); sc[m] = e; sum += e; }
    float inv = 1.0f / sum;
    #pragma unroll
    for (int m = 0; m < 64; ++m) {
        float a = sc[m] * inv;
        g_adj[tid * 64 + m] = a;
        out_adj[tid * 64 + m] = a;
    }
    int rid = rate_id[tid];
    for (int j2 = 0; j2 < 32; ++j2) {
        float v0 = gb1[2 * j2], v1 = gb1[2 * j2 + 1];
        #pragma unroll
        for (int e = 0; e < 16; ++e) {
            float rt = rate_table[rid * 16 + e];
            v0 = fmaf(rt, gw1[(6 + e) * 64 + 2 * j2], v0);
            v1 = fmaf(rt, gw1[(6 + e) * 64 + 2 * j2 + 1], v1);
        }
        g_preb1p[j2 * 64 + tid] = make_float2(v0, v1);
    }
}

// ---------------------------------------------------------------------------
// Kernel 3: packed-pair radix-2 FFT filter
// ---------------------------------------------------------------------------
__global__ void __launch_bounds__(256) fft_kernel(
    const float* __restrict__ seed, const float* __restrict__ fre,
    const float* __restrict__ fim, float* __restrict__ xfreq)
{
    __shared__ float re[2048], im[2048], twr[1024], twi[1024];
    int tid = threadIdx.x;
    int b = blockIdx.x >> 5;
    int p = blockIdx.x & 31;
    int n0 = p * 2;
    const float* src = seed + (size_t)b * T_ * N_ + n0;

    for (int j = tid; j < 1024; j += 256) {
        float s, c;
        sincosf(-6.28318530717958647692f * (float)j * (1.0f / 2048.0f), &s, &c);
        twr[j] = c; twi[j] = s;
    }
    for (int t = tid; t < 2048; t += 256) {
        float2 v = *(const float2*)(src + (size_t)t * N_);
        re[t] = v.x; im[t] = v.y;
    }

    for (int s = 10; s >= 0; --s) {
        int half = 1 << s;
        __syncthreads();
        for (int bi = tid; bi < 1024; bi += 256) {
            int j = bi & (half - 1);
            int i1 = ((bi >> s) << (s + 1)) | j;
            int i2 = i1 + half;
            int tj = j << (10 - s);
            float wr = twr[tj], wi = twi[tj];
            float ar = re[i1], ai = im[i1], br = re[i2], b2 = im[i2];
            re[i1] = ar + br; im[i1] = ai + b2;
            float dr = ar - br, di = ai - b2;
            re[i2] = dr * wr - di * wi;
            im[i2] = dr * wi + di * wr;
        }
    }
    __syncthreads();

    for (int k = tid; k <= 1024; k += 256) {
        int km = (2048 - k) & 2047;
        int pk = __brev(k) >> 21;
        int pm = __brev(km) >> 21;
        float zr = re[pk], zi = im[pk];
        float yr = re[pm], yi = im[pm];
        float x1r = 0.5f * (zr + yr), x1i = 0.5f * (zi - yi);
        float x2r = 0.5f * (zi + yi), x2i = 0.5f * (yr - zr);
        float h1r = fre[(size_t)k * N_ + n0],     h1i = fim[(size_t)k * N_ + n0];
        float h2r = fre[(size_t)k * N_ + n0 + 1], h2i = fim[(size_t)k * N_ + n0 + 1];
        float y1r = x1r * h1r - x1i * h1i, y1i = x1r * h1i + x1i * h1r;
        float y2r = x2r * h2r - x2i * h2i, y2i = x2r * h2i + x2i * h2r;
        if (k == 0 || k == 1024) { y1i = 0.f; y2i = 0.f; }
        re[pk] = y1r - y2i; im[pk] = y1i + y2r;
        if (k > 0 && k < 1024) { re[pm] = y1r + y2i; im[pm] = y2r - y1i; }
    }

    for (int s = 0; s <= 10; ++s) {
        int half = 1 << s;
        __syncthreads();
        for (int bi = tid; bi < 1024; bi += 256) {
            int j = bi & (half - 1);
            int i1 = ((bi >> s) << (s + 1)) | j;
            int i2 = i1 + half;
            int tj = j << (10 - s);
            float wr = twr[tj], wi = -twi[tj];
            float br = re[i2], b2 = im[i2];
            float tr = br * wr - b2 * wi, ti = br * wi + b2 * wr;
            float ar = re[i1], ai = im[i1];
            re[i1] = ar + tr; im[i1] = ai + ti;
            re[i2] = ar - tr; im[i2] = ai - ti;
        }
    }
    __syncthreads();

    float* dst = xfreq + (size_t)b * T_ * N_ + n0;
    const float scl = 1.0f / 2048.0f;
    for (int t = tid; t < 2048; t += 256) {
        float2 v; v.x = re[t] * scl; v.y = im[t] * scl;
        *(float2*)(dst + (size_t)t * N_) = v;
    }
}

// ---------------------------------------------------------------------------
// Kernel 4 v4: PERSISTENT fused GCN + gate MLP. grid=148, each CTA loops tiles.
// Weights + preb1 staged in smem once. tanh-approx gelu. Bias folded into acc.
// ---------------------------------------------------------------------------
#define FTH 512
#define NTILES (B_ * T_ * N_ / FTH)   // 4096
#define PGRID 148
#define SMEM_BYTES 193440

__global__ void __launch_bounds__(FTH, 1) fused_kernel(
    const float* __restrict__ seed, const float* __restrict__ mask,
    const float* __restrict__ xin, const float* __restrict__ xfreq,
    const float* __restrict__ gw1, const float* __restrict__ gw2,
    const float* __restrict__ gb2, const float* __restrict__ gw3,
    const float* __restrict__ gb3,
    const float* __restrict__ gcw1, const float* __restrict__ gcb1,
    const float* __restrict__ gcw2, const float* __restrict__ gcb2,
    float* __restrict__ out_gcn, float* __restrict__ out_imp,
    float* __restrict__ out_comp, float* __restrict__ out_gate)
{
    extern __shared__ float sm[];
    float* hs    = sm;                 // [64][512]
    float* sW2   = hs  + 64 * FTH;     // [64][64]
    float* sA    = sW2 + 64 * 64;      // [64][65]
    float* sW1   = sA  + 64 * 65;      // [6][64]
    float* sW3   = sW1 + 384;          // 128
    float* sB2   = sW3 + 128;          // 64
    float* sGc   = sB2 + 64;           // 96
    float* sCst  = sGc + 96;           // 4
    float* sPm   = sCst + 4;           // [8][64]
    float* sXg   = sPm + FTH;
    float* sXf   = sXg + FTH;
    float* sMm   = sXf + FTH;
    float* sXi   = sMm + FTH;
    float* sPreb = sXi + FTH;          // [32][64] float2 = 4096 floats

    int tid = threadIdx.x;

    // ---- stage weights once ----
    for (int i = tid; i < 4096; i += FTH) sW2[i] = gw2[i];
    for (int i = tid; i < 4096; i += FTH) sA[(i >> 6) * 65 + (i & 63)] = g_adj[i];
    for (int i = tid; i < 2048; i += FTH) ((float2*)sPreb)[i] = g_preb1p[i];
    if (tid < 384) sW1[tid] = gw1[tid];
    if (tid < 128) sW3[tid] = gw3[tid];
    if (tid < 64) sB2[tid] = gb2[tid];
    if (tid < 32) { sGc[tid] = gcw1[tid]; sGc[32 + tid] = gcb1[tid]; sGc[64 + tid] = gcw2[tid]; }
    if (tid == 0) { sCst[0] = gcb2[0]; sCst[1] = gb3[0]; sCst[2] = gb3[1]; }

    int n  = tid & 63;
    int r  = tid >> 6;       // 0..7
    int jg = tid & 7;        // phase B col group
    int rg = tid >> 3;       // phase B row group

    for (int tile = blockIdx.x; tile < NTILES; tile += gridDim.x) {
        __syncthreads();     // staging done / protect smem reuse across tiles

        int gidx = tile * FTH + tid;
        float s  = seed[gidx];
        float mm = mask[gidx];
        float xf = xfreq[gidx];
        float xi = xin[gidx];

        // phi(s)
        float pv = 0.f;
        #pragma unroll
        for (int h = 0; h < 32; ++h)
            pv = fmaf(sGc[64 + h], gelu_t(fmaf(s, sGc[h], sGc[32 + h])), pv);
        sPm[r * 64 + n] = pv;
        __syncthreads();

        // x_gcn
        float xg = sCst[0];
        #pragma unroll 8
        for (int m = 0; m < 64; ++m)
            xg = fmaf(sA[n * 65 + m], sPm[r * 64 + m], xg);

        sXg[tid] = xg; sXf[tid] = xf; sMm[tid] = mm; sXi[tid] = xi;
        out_gcn[gidx] = xg;

        u64 u0 = pk2(s, s), u1 = pk2(mm, mm), u2 = pk2(xg, xg);
        u64 u3 = pk2(xf, xf), u4 = pk2(xg - s, xg - s), u5 = pk2(xf - s, xf - s);

        const float4* W1v = (const float4*)sW1;
        #pragma unroll
        for (int jq = 0; jq < 16; ++jq) {
            float2 pA = ((float2*)sPreb)[(2 * jq) * 64 + n];
            float2 pB = ((float2*)sPreb)[(2 * jq + 1) * 64 + n];
            u64 a0 = pk2(pA.x, pA.y);
            u64 a1 = pk2(pB.x, pB.y);
            float4 w;
            u64 wp;
            w = W1v[0 * 16 + jq]; wp = pk2(w.x, w.y); a0 = ffma2(u0, wp, a0); wp = pk2(w.z, w.w); a1 = ffma2(u0, wp, a1);
            w = W1v[1 * 16 + jq]; wp = pk2(w.x, w.y); a0 = ffma2(u1, wp, a0); wp = pk2(w.z, w.w); a1 = ffma2(u1, wp, a1);
            w = W1v[2 * 16 + jq]; wp = pk2(w.x, w.y); a0 = ffma2(u2, wp, a0); wp = pk2(w.z, w.w); a1 = ffma2(u2, wp, a1);
            w = W1v[3 * 16 + jq]; wp = pk2(w.x, w.y); a0 = ffma2(u3, wp, a0); wp = pk2(w.z, w.w); a1 = ffma2(u3, wp, a1);
            w = W1v[4 * 16 + jq]; wp = pk2(w.x, w.y); a0 = ffma2(u4, wp, a0); wp = pk2(w.z, w.w); a1 = ffma2(u4, wp, a1);
            w = W1v[5 * 16 + jq]; wp = pk2(w.x, w.y); a0 = ffma2(u5, wp, a0); wp = pk2(w.z, w.w); a1 = ffma2(u5, wp, a1);
            float v0, v1, v2, v3;
            upk2(a0, v0, v1); upk2(a1, v2, v3);
            hs[(4 * jq + 0) * FTH + tid] = gelu_t(v0);
            hs[(4 * jq + 1) * FTH + tid] = gelu_t(v1);
            hs[(4 * jq + 2) * FTH + tid] = gelu_t(v2);
            hs[(4 * jq + 3) * FTH + tid] = gelu_t(v3);
        }
        __syncthreads();

        // ---- Phase B: layer2 GEMM, 8x8 FFMA2 tile, bias folded into acc ----
        int j0 = jg * 8;
        u64 binit[4];
        #pragma unroll
        for (int p = 0; p < 4; ++p) binit[p] = pk2(sB2[j0 + 2 * p], sB2[j0 + 2 * p + 1]);

        u64 acc[8][4];
        #pragma unroll
        for (int c = 0; c < 8; ++c)
            #pragma unroll
            for (int p = 0; p < 4; ++p) acc[c][p] = binit[p];

        const float* hbase = hs + rg * 8;
        const float* wbase = sW2 + jg * 8;
        #pragma unroll 4
        for (int k = 0; k < 64; ++k) {
            float4 ha = *(const float4*)(hbase + k * FTH);
            float4 hb = *(const float4*)(hbase + k * FTH + 4);
            ulonglong2 wa = *(const ulonglong2*)(wbase + k * 64);
            ulonglong2 wb = *(const ulonglong2*)(wbase + k * 64 + 4);
            u64 hd;
            hd = pk2(ha.x, ha.x);
            acc[0][0] = ffma2(hd, wa.x, acc[0][0]); acc[0][1] = ffma2(hd, wa.y, acc[0][1]);
            acc[0][2] = ffma2(hd, wb.x, acc[0][2]); acc[0][3] = ffma2(hd, wb.y, acc[0][3]);
            hd = pk2(ha.y, ha.y);
            acc[1][0] = ffma2(hd, wa.x, acc[1][0]); acc[1][1] = ffma2(hd, wa.y, acc[1][1]);
            acc[1][2] = ffma2(hd, wb.x, acc[1][2]); acc[1][3] = ffma2(hd, wb.y, acc[1][3]);
            hd = pk2(ha.z, ha.z);
            acc[2][0] = ffma2(hd, wa.x, acc[2][0]); acc[2][1] = ffma2(hd, wa.y, acc[2][1]);
            acc[2][2] = ffma2(hd, wb.x, acc[2][2]); acc[2][3] = ffma2(hd, wb.y, acc[2][3]);
            hd = pk2(ha.w, ha.w);
            acc[3][0] = ffma2(hd, wa.x, acc[3][0]); acc[3][1] = ffma2(hd, wa.y, acc[3][1]);
            acc[3][2] = ffma2(hd, wb.x, acc[3][2]); acc[3][3] = ffma2(hd, wb.y, acc[3][3]);
            hd = pk2(hb.x, hb.x);
            acc[4][0] = ffma2(hd, wa.x, acc[4][0]); acc[4][1] = ffma2(hd, wa.y, acc[4][1]);
            acc[4][2] = ffma2(hd, wb.x, acc[4][2]); acc[4][3] = ffma2(hd, wb.y, acc[4][3]);
            hd = pk2(hb.y, hb.y);
            acc[5][0] = ffma2(hd, wa.x, acc[5][0]); acc[5][1] = ffma2(hd, wa.y, acc[5][1]);
            acc[5][2] = ffma2(hd, wb.x, acc[5][2]); acc[5][3] = ffma2(hd, wb.y, acc[5][3]);
            hd = pk2(hb.z, hb.z);
            acc[6][0] = ffma2(hd, wa.x, acc[6][0]); acc[6][1] = ffma2(hd, wa.y, acc[6][1]);
            acc[6][2] = ffma2(hd, wb.x, acc[6][2]); acc[6][3] = ffma2(hd, wb.y, acc[6][3]);
            hd = pk2(hb.w, hb.w);
            acc[7][0] = ffma2(hd, wa.x, acc[7][0]); acc[7][1] = ffma2(hd, wa.y, acc[7][1]);
            acc[7][2] = ffma2(hd, wb.x, acc[7][2]); acc[7][3] = ffma2(hd, wb.y, acc[7][3]);
        }

        float myLg0 = 0.f, myLg1 = 0.f;
        #pragma unroll
        for (int c = 0; c < 8; ++c) {
            float lg0 = 0.f, lg1 = 0.f;
            #pragma unroll
            for (int p = 0; p < 4; ++p) {
                float a0, a1;
                upk2(acc[c][p], a0, a1);
                int j = j0 + 2 * p;
                float h2a = gelu_t(a0);
                float h2b = gelu_t(a1);
                lg0 = fmaf(h2a, sW3[2 * j],     lg0); lg1 = fmaf(h2a, sW3[2 * j + 1], lg1);
                lg0 = fmaf(h2b, sW3[2 * j + 2], lg0); lg1 = fmaf(h2b, sW3[2 * j + 3], lg1);
            }
            lg0 += __shfl_xor_sync(0xffffffffu, lg0, 4);
            lg1 += __shfl_xor_sync(0xffffffffu, lg1, 4);
            lg0 += __shfl_xor_sync(0xffffffffu, lg0, 2);
            lg1 += __shfl_xor_sync(0xffffffffu, lg1, 2);
            lg0 += __shfl_xor_sync(0xffffffffu, lg0, 1);
            lg1 += __shfl_xor_sync(0xffffffffu, lg1, 1);
            if (jg == c) { myLg0 = lg0; myLg1 = lg1; }
        }

        int row = rg * 8 + jg;
        int og  = tile * FTH + row;
        float lg0 = myLg0 + sCst[1];
        float lg1 = myLg1 + sCst[2];
        float mx = fmaxf(lg0, lg1);
        float e0 = __expf(lg0 - mx), e1 = __expf(lg1 - mx);
        float inv = __fdividef(1.0f, e0 + e1);
        float g0 = e0 * inv, g1 = e1 * inv;

        float xgr = sXg[row], xfr = sXf[row], mmr = sMm[row], xir = sXi[row];
        float imputed  = fmaf(g0, xgr, g1 * xfr);
        float complete = (mmr != 0.f) ? imputed : xir;

        out_imp[og]  = imputed;
        out_comp[og] = complete;
        float2 gv; gv.x = g0; gv.y = g1;
        *(float2*)(out_gate + (size_t)og * 2) = gv;
    }
}

// ---------------------------------------------------------------------------
extern "C" void kernel_launch(void* const* d_in, const int* in_sizes, int n_in,
                              void* d_out, int out_size)
{
    const float* x     = (const float*)d_in[0];
    const float* mask  = (const float*)d_in[1];
    const int*   rid   = (const int*)  d_in[2];
    const float* emb   = (const float*)d_in[3];
    const float* gcw1  = (const float*)d_in[4];
    const float* gcb1  = (const float*)d_in[5];
    const float* gcw2  = (const float*)d_in[6];
    const float* gcb2  = (const float*)d_in[7];
    const float* fre   = (const float*)d_in[8];
    const float* fim   = (const float*)d_in[9];
    const float* rtab  = (const float*)d_in[10];
    const float* gw1   = (const float*)d_in[11];
    const float* gb1   = (const float*)d_in[12];
    const float* gw2   = (const float*)d_in[13];
    const float* gb2   = (const float*)d_in[14];
    const float* gw3   = (const float*)d_in[15];
    const float* gb3   = (const float*)d_in[16];
    float* out = (float*)d_out;

    cudaFuncSetAttribute(fused_kernel, cudaFuncAttributeMaxDynamicSharedMemorySize, SMEM_BYTES);

    adj_kernel<<<1, 64>>>(emb, rid, rtab, gw1, gb1, out + ADJ_OFF);
    fill_sum_kernel<<<256, 256>>>(x, mask);
    fill_scan_kernel<<<4, 256>>>();
    fill_out_kernel<<<256, 256>>>(x, mask, out + SEED_OFF);
    fft_kernel<<<B_ * N_ / 2, 256>>>(out + SEED_OFF, fre, fim, out + FREQ_OFF);
    fused_kernel<<<PGRID, FTH, SMEM_BYTES>>>(
        out + SEED_OFF, mask, x, out + FREQ_OFF,
        gw1, gw2, gb2, gw3, gb3,
        gcw1, gcb1, gcw2, gcb2,
        out + GCN_OFF, out + IMP_OFF, out + COMP_OFF, out + GATE_OFF);
}

// round 5
// speedup vs baseline: 2.3306x; 1.5233x over previous
#include <cuda_runtime.h>
#include <cuda_bf16.h>
#include <math.h>

#define B_ 16
#define T_ 2048
#define N_ 64

// Output layout (flattened tuple in order)
#define SEED_OFF 0
#define GCN_OFF  2097152
#define FREQ_OFF 4194304
#define IMP_OFF  6291456
#define COMP_OFF 8388608
#define GATE_OFF 10485760
#define ADJ_OFF  14680064

typedef unsigned long long u64;
typedef unsigned int u32;

// Scratch (static device arrays: allowed)
__device__ float  g_adj[N_ * N_];
__device__ float2 g_preb1p[32 * N_];
__device__ float  g_first[65536], g_last[65536];
__device__ unsigned char g_has[65536];
__device__ float  g_pref[65536], g_suf[65536];
__device__ unsigned char g_prefh[65536], g_sufh[65536];

// ---- packed f32x2 helpers ---------------------------------------------------
__device__ __forceinline__ u64 pk2(float lo, float hi) {
    u64 r; asm("mov.b64 %0, {%1, %2};" : "=l"(r) : "f"(lo), "f"(hi)); return r;
}
__device__ __forceinline__ void upk2(u64 v, float& lo, float& hi) {
    asm("mov.b64 {%0, %1}, %2;" : "=f"(lo), "=f"(hi) : "l"(v));
}
__device__ __forceinline__ u64 ffma2(u64 a, u64 b, u64 c) {
    u64 d; asm("fma.rn.f32x2 %0, %1, %2, %3;" : "=l"(d) : "l"(a), "l"(b), "l"(c)); return d;
}
__device__ __forceinline__ u64 mul2(u64 a, u64 b) {
    u64 d; asm("mul.rn.f32x2 %0, %1, %2;" : "=l"(d) : "l"(a), "l"(b)); return d;
}

__device__ __forceinline__ float tanh_ap(float x) {
    float t; asm("tanh.approx.f32 %0, %1;" : "=f"(t) : "f"(x)); return t;
}

// scalar tanh-approx gelu
__device__ __forceinline__ float gelu_t(float x) {
    float x2 = x * x;
    float inner = fmaf(x2, 0.035677408136f, 0.7978845608028654f);
    float b = x * inner;
    float t = tanh_ap(b);
    float hx = 0.5f * x;
    return fmaf(hx, t, hx);
}

// packed pairwise gelu: 5 packed fma-pipe ops + 2 MUFU
__device__ __forceinline__ u64 gelu2(u64 x) {
    const u64 C1 = pk2(0.035677408136f, 0.035677408136f);
    const u64 C0 = pk2(0.7978845608028654f, 0.7978845608028654f);
    const u64 H  = pk2(0.5f, 0.5f);
    u64 x2 = mul2(x, x);
    u64 inner = ffma2(x2, C1, C0);
    u64 b = mul2(x, inner);
    float b0, b1; upk2(b, b0, b1);
    u64 t = pk2(tanh_ap(b0), tanh_ap(b1));
    u64 hx = mul2(x, H);
    return ffma2(hx, t, hx);
}

__device__ __forceinline__ u32 to_tf32(float v) {
    u32 r; asm("cvt.rna.tf32.f32 %0, %1;" : "=r"(r) : "f"(v)); return r;
}

__device__ __forceinline__ void mma_tf32(float* d,
    u32 a0, u32 a1, u32 a2, u32 a3, u32 b0, u32 b1)
{
    asm("mma.sync.aligned.m16n8k8.row.col.f32.tf32.tf32.f32 "
        "{%0,%1,%2,%3}, {%4,%5,%6,%7}, {%8,%9}, {%0,%1,%2,%3};"
        : "+f"(d[0]), "+f"(d[1]), "+f"(d[2]), "+f"(d[3])
        : "r"(a0), "r"(a1), "r"(a2), "r"(a3), "r"(b0), "r"(b1));
}

// ---------------------------------------------------------------------------
// Fill stage 1
// ---------------------------------------------------------------------------
__global__ void __launch_bounds__(256) fill_sum_kernel(
    const float* __restrict__ x, const float* __restrict__ mask)
{
    int g = blockIdx.x * 256 + threadIdx.x;
    int n = g & 63;
    int c = (g >> 6) & 63;
    int b = g >> 12;
    int base = ((b * T_) + c * 32) * N_ + n;
    float first = 0.f, last = 0.f; bool has = false;
    #pragma unroll
    for (int t = 0; t < 32; ++t) {
        int idx = base + t * N_;
        float v = x[idx];
        bool obs = (mask[idx] == 0.f);
        if (obs) { if (!has) first = v; last = v; has = true; }
    }
    g_first[g] = first; g_last[g] = last; g_has[g] = (unsigned char)has;
}

// ---------------------------------------------------------------------------
// Fill stage 2
// ---------------------------------------------------------------------------
__global__ void __launch_bounds__(256) fill_scan_kernel()
{
    int g = blockIdx.x * 256 + threadIdx.x;
    int b = g >> 6, n = g & 63;
    int base = b * 4096 + n;
    float pv = 0.f; bool ph = false;
    #pragma unroll 8
    for (int c = 0; c < 64; ++c) {
        int i = base + c * 64;
        g_pref[i] = pv; g_prefh[i] = (unsigned char)ph;
        if (g_has[i]) { pv = g_last[i]; ph = true; }
    }
    float sv = 0.f; bool sh = false;
    #pragma unroll 8
    for (int c = 63; c >= 0; --c) {
        int i = base + c * 64;
        g_suf[i] = sv; g_sufh[i] = (unsigned char)sh;
        if (g_has[i]) { sv = g_first[i]; sh = true; }
    }
}

// ---------------------------------------------------------------------------
// Fill stage 3
// ---------------------------------------------------------------------------
__global__ void __launch_bounds__(256) fill_out_kernel(
    const float* __restrict__ x, const float* __restrict__ mask,
    float* __restrict__ seed)
{
    int g = blockIdx.x * 256 + threadIdx.x;
    int n = g & 63;
    int c = (g >> 6) & 63;
    int b = g >> 12;
    int base = ((b * T_) + c * 32) * N_ + n;

    float fv = g_pref[g]; bool fh = (bool)g_prefh[g];
    float vals[32];
    unsigned obsm = 0u, fam = 0u;
    #pragma unroll
    for (int t = 0; t < 32; ++t) {
        int idx = base + t * N_;
        float v = x[idx];
        bool obs = (mask[idx] == 0.f);
        if (obs) { fv = v; fh = true; obsm |= (1u << t); }
        vals[t] = fv;
        if (fh) fam |= (1u << t);
    }
    float bv = g_suf[g]; bool bh = (bool)g_sufh[g];
    #pragma unroll
    for (int t = 31; t >= 0; --t) {
        bool obs = (obsm >> t) & 1u;
        bool fa  = (fam  >> t) & 1u;
        float v = vals[t];
        if (obs) { bv = v; bh = true; }
        float out;
        if (obs)            out = v;
        else if (fa && bh)  out = 0.5f * (v + bv);
        else if (fa)        out = v;
        else if (bh)        out = bv;
        else                out = 0.f;
        seed[base + t * N_] = out;
    }
}

// ---------------------------------------------------------------------------
// Kernel 2: adjacency + rate-embed pre-bias
// ---------------------------------------------------------------------------
__global__ void __launch_bounds__(64) adj_kernel(
    const float* __restrict__ emb, const int* __restrict__ rate_id,
    const float* __restrict__ rate_table, const float* __restrict__ gw1,
    const float* __restrict__ gb1, float* __restrict__ out_adj)
{
    __shared__ float sE[64 * 32];
    int tid = threadIdx.x;
    for (int i = tid; i < 64 * 32; i += 64) sE[i] = emb[i];
    __syncthreads();

    float sc[64];
    float mx = -1e30f;
    #pragma unroll
    for (int m = 0; m < 64; ++m) {
        float d = 0.f;
        #pragma unroll
        for (int h = 0; h < 32; ++h) d = fmaf(sE[tid * 32 + h], sE[m * 32 + h], d);
        d = fmaxf(d, 0.f);
        sc[m] = d; mx = fmaxf(mx, d);
    }
    float sum = 0.f;
    #pragma unroll
    for (int m = 0; m < 64; ++m) { float e = __expf(sc[m] - mx); sc[m] = e; sum += e; }
    float inv = 1.0f / sum;
    #pragma unroll
    for (int m = 0; m < 64; ++m) {
        float a = sc[m] * inv;
        g_adj[tid * 64 + m] = a;
        out_adj[tid * 64 + m] = a;
    }
    int rid = rate_id[tid];
    for (int j2 = 0; j2 < 32; ++j2) {
        float v0 = gb1[2 * j2], v1 = gb1[2 * j2 + 1];
        #pragma unroll
        for (int e = 0; e < 16; ++e) {
            float rt = rate_table[rid * 16 + e];
            v0 = fmaf(rt, gw1[(6 + e) * 64 + 2 * j2], v0);
            v1 = fmaf(rt, gw1[(6 + e) * 64 + 2 * j2 + 1], v1);
        }
        g_preb1p[j2 * 64 + tid] = make_float2(v0, v1);
    }
}

// ---------------------------------------------------------------------------
// Kernel 3: packed-pair radix-2 FFT filter
// ---------------------------------------------------------------------------
__global__ void __launch_bounds__(256) fft_kernel(
    const float* __restrict__ seed, const float* __restrict__ fre,
    const float* __restrict__ fim, float* __restrict__ xfreq)
{
    __shared__ float re[2048], im[2048], twr[1024], twi[1024];
    int tid = threadIdx.x;
    int b = blockIdx.x >> 5;
    int p = blockIdx.x & 31;
    int n0 = p * 2;
    const float* src = seed + (size_t)b * T_ * N_ + n0;

    for (int j = tid; j < 1024; j += 256) {
        float s, c;
        sincosf(-6.28318530717958647692f * (float)j * (1.0f / 2048.0f), &s, &c);
        twr[j] = c; twi[j] = s;
    }
    for (int t = tid; t < 2048; t += 256) {
        float2 v = *(const float2*)(src + (size_t)t * N_);
        re[t] = v.x; im[t] = v.y;
    }

    for (int s = 10; s >= 0; --s) {
        int half = 1 << s;
        __syncthreads();
        for (int bi = tid; bi < 1024; bi += 256) {
            int j = bi & (half - 1);
            int i1 = ((bi >> s) << (s + 1)) | j;
            int i2 = i1 + half;
            int tj = j << (10 - s);
            float wr = twr[tj], wi = twi[tj];
            float ar = re[i1], ai = im[i1], br = re[i2], b2 = im[i2];
            re[i1] = ar + br; im[i1] = ai + b2;
            float dr = ar - br, di = ai - b2;
            re[i2] = dr * wr - di * wi;
            im[i2] = dr * wi + di * wr;
        }
    }
    __syncthreads();

    for (int k = tid; k <= 1024; k += 256) {
        int km = (2048 - k) & 2047;
        int pk = __brev(k) >> 21;
        int pm = __brev(km) >> 21;
        float zr = re[pk], zi = im[pk];
        float yr = re[pm], yi = im[pm];
        float x1r = 0.5f * (zr + yr), x1i = 0.5f * (zi - yi);
        float x2r = 0.5f * (zi + yi), x2i = 0.5f * (yr - zr);
        float h1r = fre[(size_t)k * N_ + n0],     h1i = fim[(size_t)k * N_ + n0];
        float h2r = fre[(size_t)k * N_ + n0 + 1], h2i = fim[(size_t)k * N_ + n0 + 1];
        float y1r = x1r * h1r - x1i * h1i, y1i = x1r * h1i + x1i * h1r;
        float y2r = x2r * h2r - x2i * h2i, y2i = x2r * h2i + x2i * h2r;
        if (k == 0 || k == 1024) { y1i = 0.f; y2i = 0.f; }
        re[pk] = y1r - y2i; im[pk] = y1i + y2r;
        if (k > 0 && k < 1024) { re[pm] = y1r + y2i; im[pm] = y2r - y1i; }
    }

    for (int s = 0; s <= 10; ++s) {
        int half = 1 << s;
        __syncthreads();
        for (int bi = tid; bi < 1024; bi += 256) {
            int j = bi & (half - 1);
            int i1 = ((bi >> s) << (s + 1)) | j;
            int i2 = i1 + half;
            int tj = j << (10 - s);
            float wr = twr[tj], wi = -twi[tj];
            float br = re[i2], b2 = im[i2];
            float tr = br * wr - b2 * wi, ti = br * wi + b2 * wr;
            float ar = re[i1], ai = im[i1];
            re[i1] = ar + tr; im[i1] = ai + ti;
            re[i2] = ar - tr; im[i2] = ai - ti;
        }
    }
    __syncthreads();

    float* dst = xfreq + (size_t)b * T_ * N_ + n0;
    const float scl = 1.0f / 2048.0f;
    for (int t = tid; t < 2048; t += 256) {
        float2 v; v.x = re[t] * scl; v.y = im[t] * scl;
        *(float2*)(dst + (size_t)t * N_) = v;
    }
}

// ---------------------------------------------------------------------------
// Kernel 4 v5: persistent; layer2 on tf32 mma.sync; packed gelu everywhere.
// hs: [64 k][512+8 rows] tf32 bits.  w2: [64 k][72] tf32 bits.
// Phase B: warp w owns rows w*32..w*32+31; 2 m16 tiles x 8 n8 tiles x 8 k8.
// ---------------------------------------------------------------------------
#define FTH 512
#define HS_S 520
#define W2_S 72
#define NTILES (B_ * T_ * N_ / FTH)   // 4096
#define PGRID 148
// floats: hs 33280 + w2 4608 + adj 4224 + preb 4096 + w1 384 + w3e/o 128
//         + b2 64 + gc 96 + pm 512 + xg/xf/mm/xi 2048 + cst 4  = 49444
#define SMEM_BYTES (49444 * 4)

__global__ void __launch_bounds__(FTH, 1) fused_kernel(
    const float* __restrict__ seed, const float* __restrict__ mask,
    const float* __restrict__ xin, const float* __restrict__ xfreq,
    const float* __restrict__ gw1, const float* __restrict__ gw2,
    const float* __restrict__ gb2, const float* __restrict__ gw3,
    const float* __restrict__ gb3,
    const float* __restrict__ gcw1, const float* __restrict__ gcb1,
    const float* __restrict__ gcw2, const float* __restrict__ gcb2,
    float* __restrict__ out_gcn, float* __restrict__ out_imp,
    float* __restrict__ out_comp, float* __restrict__ out_gate)
{
    extern __shared__ float sm[];
    float* hs    = sm;                    // [64][520] (tf32 bits)
    float* sW2   = hs    + 64 * HS_S;     // [64][72] (tf32 bits)
    float* sA    = sW2   + 64 * W2_S;     // [64][66]
    float* sPreb = sA    + 64 * 66;       // [32][64] float2
    float* sW1   = sPreb + 4096;          // [6][64]
    float* sW3e  = sW1   + 384;           // [32] float2
    float* sW3o  = sW3e  + 64;            // [32] float2
    float* sB2   = sW3o  + 64;            // [64]
    float* sGc   = sB2   + 64;            // [96]
    float* sPm   = sGc   + 96;            // [8][64]
    float* sXg   = sPm   + FTH;
    float* sXf   = sXg   + FTH;
    float* sMm   = sXf   + FTH;
    float* sXi   = sMm   + FTH;
    float* sCst  = sXi   + FTH;           // [4]

    int tid = threadIdx.x;

    // ---- stage weights once ----
    for (int i = tid; i < 4096; i += FTH) {
        int k = i >> 6, j = i & 63;
        ((u32*)sW2)[k * W2_S + j] = to_tf32(gw2[i]);
    }
    for (int i = tid; i < 4096; i += FTH) sA[(i >> 6) * 66 + (i & 63)] = g_adj[i];
    for (int i = tid; i < 2048; i += FTH) ((float2*)sPreb)[i] = g_preb1p[i];
    if (tid < 384) sW1[tid] = gw1[tid];
    if (tid < 32) {
        ((float2*)sW3e)[tid] = make_float2(gw3[4 * tid],     gw3[4 * tid + 2]);
        ((float2*)sW3o)[tid] = make_float2(gw3[4 * tid + 1], gw3[4 * tid + 3]);
        sGc[tid] = gcw1[tid]; sGc[32 + tid] = gcb1[tid]; sGc[64 + tid] = gcw2[tid];
    }
    if (tid < 64) sB2[tid] = gb2[tid];
    if (tid == 0) { sCst[0] = gcb2[0]; sCst[1] = gb3[0]; sCst[2] = gb3[1]; }

    int n    = tid & 63;
    int r    = tid >> 6;      // 0..7
    int lane = tid & 31;
    int warp = tid >> 5;      // 0..15
    int m0   = warp * 32;
    int qr   = lane >> 2;     // quad row 0..7
    int qc   = lane & 3;      // quad col 0..3

    for (int tile = blockIdx.x; tile < NTILES; tile += gridDim.x) {
        __syncthreads();

        int gidx = tile * FTH + tid;
        float s  = seed[gidx];
        float mm = mask[gidx];
        float xf = xfreq[gidx];
        float xi = xin[gidx];

        // ---- phi(s), packed pairs ----
        u64 sp = pk2(s, s);
        u64 accp = pk2(0.f, 0.f);
        const u64* gcW = (const u64*)sGc;
        const u64* gcB = (const u64*)(sGc + 32);
        const u64* gcV = (const u64*)(sGc + 64);
        #pragma unroll
        for (int hq = 0; hq < 16; ++hq) {
            u64 pre = ffma2(sp, gcW[hq], gcB[hq]);
            accp = ffma2(gelu2(pre), gcV[hq], accp);
        }
        float p0, p1; upk2(accp, p0, p1);
        sPm[r * 64 + n] = p0 + p1;
        __syncthreads();

        // ---- x_gcn (packed matvec) ----
        u64 xgp = pk2(0.f, 0.f);
        const u64* arow = (const u64*)(sA + n * 66);
        const u64* prow = (const u64*)(sPm + r * 64);
        #pragma unroll 8
        for (int m2 = 0; m2 < 32; ++m2)
            xgp = ffma2(arow[m2], prow[m2], xgp);
        float xg0, xg1; upk2(xgp, xg0, xg1);
        float xg = xg0 + xg1 + sCst[0];

        sXg[tid] = xg; sXf[tid] = xf; sMm[tid] = mm; sXi[tid] = xi;
        out_gcn[gidx] = xg;

        // ---- layer1 (packed) -> hs as tf32 ----
        u64 u0 = pk2(s, s), u1 = pk2(mm, mm), u2 = pk2(xg, xg);
        u64 u3 = pk2(xf, xf), u4 = pk2(xg - s, xg - s), u5 = pk2(xf - s, xf - s);
        const float4* W1v = (const float4*)sW1;
        u32* hsu = (u32*)hs;
        #pragma unroll
        for (int jq = 0; jq < 16; ++jq) {
            float2 pA = ((float2*)sPreb)[(2 * jq) * 64 + n];
            float2 pB = ((float2*)sPreb)[(2 * jq + 1) * 64 + n];
            u64 a0 = pk2(pA.x, pA.y);
            u64 a1 = pk2(pB.x, pB.y);
            float4 w; u64 wp;
            w = W1v[0 * 16 + jq]; wp = pk2(w.x, w.y); a0 = ffma2(u0, wp, a0); wp = pk2(w.z, w.w); a1 = ffma2(u0, wp, a1);
            w = W1v[1 * 16 + jq]; wp = pk2(w.x, w.y); a0 = ffma2(u1, wp, a0); wp = pk2(w.z, w.w); a1 = ffma2(u1, wp, a1);
            w = W1v[2 * 16 + jq]; wp = pk2(w.x, w.y); a0 = ffma2(u2, wp, a0); wp = pk2(w.z, w.w); a1 = ffma2(u2, wp, a1);
            w = W1v[3 * 16 + jq]; wp = pk2(w.x, w.y); a0 = ffma2(u3, wp, a0); wp = pk2(w.z, w.w); a1 = ffma2(u3, wp, a1);
            w = W1v[4 * 16 + jq]; wp = pk2(w.x, w.y); a0 = ffma2(u4, wp, a0); wp = pk2(w.z, w.w); a1 = ffma2(u4, wp, a1);
            w = W1v[5 * 16 + jq]; wp = pk2(w.x, w.y); a0 = ffma2(u5, wp, a0); wp = pk2(w.z, w.w); a1 = ffma2(u5, wp, a1);
            u64 g0 = gelu2(a0);
            u64 g1 = gelu2(a1);
            float v0, v1, v2, v3;
            upk2(g0, v0, v1); upk2(g1, v2, v3);
            hsu[(4 * jq + 0) * HS_S + tid] = to_tf32(v0);
            hsu[(4 * jq + 1) * HS_S + tid] = to_tf32(v1);
            hsu[(4 * jq + 2) * HS_S + tid] = to_tf32(v2);
            hsu[(4 * jq + 3) * HS_S + tid] = to_tf32(v3);
        }
        __syncthreads();

        // ---- Phase B: layer2 via tf32 mma ----
        float acc[2][8][4];
        #pragma unroll
        for (int n8 = 0; n8 < 8; ++n8) {
            int j0 = n8 * 8 + qc * 2;
            float2 bb = *(const float2*)(sB2 + j0);
            #pragma unroll
            for (int mt = 0; mt < 2; ++mt) {
                acc[mt][n8][0] = bb.x; acc[mt][n8][1] = bb.y;
                acc[mt][n8][2] = bb.x; acc[mt][n8][3] = bb.y;
            }
        }

        const u32* hsub = (const u32*)hs;
        const u32* w2u  = (const u32*)sW2;
        int ar = m0 + qr;
        #pragma unroll
        for (int k8 = 0; k8 < 8; ++k8) {
            int kb = k8 * 8 + qc;
            const u32* h0 = hsub + kb * HS_S;
            const u32* h4 = hsub + (kb + 4) * HS_S;
            u32 a00 = h0[ar],      a01 = h0[ar + 8],  a02 = h4[ar],      a03 = h4[ar + 8];
            u32 a10 = h0[ar + 16], a11 = h0[ar + 24], a12 = h4[ar + 16], a13 = h4[ar + 24];
            const u32* b0p = w2u + kb * W2_S + qr;
            const u32* b1p = w2u + (kb + 4) * W2_S + qr;
            #pragma unroll
            for (int n8 = 0; n8 < 8; ++n8) {
                u32 b0 = b0p[n8 * 8];
                u32 b1 = b1p[n8 * 8];
                mma_tf32(acc[0][n8], a00, a01, a02, a03, b0, b1);
                mma_tf32(acc[1][n8], a10, a11, a12, a13, b0, b1);
            }
        }

        // ---- epilogue: gelu(h2) + layer3 + quad reduce + outputs ----
        const float2* w3e = (const float2*)sW3e;
        const float2* w3o = (const float2*)sW3o;
        #pragma unroll
        for (int mt = 0; mt < 2; ++mt) {
            #pragma unroll
            for (int half = 0; half < 2; ++half) {
                u64 lgP0 = pk2(0.f, 0.f), lgP1 = pk2(0.f, 0.f);
                #pragma unroll
                for (int n8 = 0; n8 < 8; ++n8) {
                    int j2 = n8 * 4 + qc;       // pair index j0/2
                    u64 a = pk2(acc[mt][n8][2 * half], acc[mt][n8][2 * half + 1]);
                    u64 g = gelu2(a);
                    float2 we = w3e[j2], wo = w3o[j2];
                    lgP0 = ffma2(g, pk2(we.x, we.y), lgP0);
                    lgP1 = ffma2(g, pk2(wo.x, wo.y), lgP1);
                }
                float l0a, l0b, l1a, l1b;
                upk2(lgP0, l0a, l0b); upk2(lgP1, l1a, l1b);
                float lg0 = l0a + l0b, lg1 = l1a + l1b;
                lg0 += __shfl_xor_sync(0xffffffffu, lg0, 1);
                lg0 += __shfl_xor_sync(0xffffffffu, lg0, 2);
                lg1 += __shfl_xor_sync(0xffffffffu, lg1, 1);
                lg1 += __shfl_xor_sync(0xffffffffu, lg1, 2);

                if (qc == half + 2 * mt) {
                    int row = m0 + qr + 8 * half + 16 * mt;
                    int og  = tile * FTH + row;
                    lg0 += sCst[1]; lg1 += sCst[2];
                    float mxv = fmaxf(lg0, lg1);
                    float e0 = __expf(lg0 - mxv), e1 = __expf(lg1 - mxv);
                    float inv = __fdividef(1.0f, e0 + e1);
                    float g0 = e0 * inv, g1 = e1 * inv;
                    float xgr = sXg[row], xfr = sXf[row], mmr = sMm[row], xir = sXi[row];
                    float imputed  = fmaf(g0, xgr, g1 * xfr);
                    float complete = (mmr != 0.f) ? imputed : xir;
                    out_imp[og]  = imputed;
                    out_comp[og] = complete;
                    float2 gv; gv.x = g0; gv.y = g1;
                    *(float2*)(out_gate + (size_t)og * 2) = gv;
                }
            }
        }
    }
}

// ---------------------------------------------------------------------------
extern "C" void kernel_launch(void* const* d_in, const int* in_sizes, int n_in,
                              void* d_out, int out_size)
{
    const float* x     = (const float*)d_in[0];
    const float* mask  = (const float*)d_in[1];
    const int*   rid   = (const int*)  d_in[2];
    const float* emb   = (const float*)d_in[3];
    const float* gcw1  = (const float*)d_in[4];
    const float* gcb1  = (const float*)d_in[5];
    const float* gcw2  = (const float*)d_in[6];
    const float* gcb2  = (const float*)d_in[7];
    const float* fre   = (const float*)d_in[8];
    const float* fim   = (const float*)d_in[9];
    const float* rtab  = (const float*)d_in[10];
    const float* gw1   = (const float*)d_in[11];
    const float* gb1   = (const float*)d_in[12];
    const float* gw2   = (const float*)d_in[13];
    const float* gb2   = (const float*)d_in[14];
    const float* gw3   = (const float*)d_in[15];
    const float* gb3   = (const float*)d_in[16];
    float* out = (float*)d_out;

    cudaFuncSetAttribute(fused_kernel, cudaFuncAttributeMaxDynamicSharedMemorySize, SMEM_BYTES);

    adj_kernel<<<1, 64>>>(emb, rid, rtab, gw1, gb1, out + ADJ_OFF);
    fill_sum_kernel<<<256, 256>>>(x, mask);
    fill_scan_kernel<<<4, 256>>>();
    fill_out_kernel<<<256, 256>>>(x, mask, out + SEED_OFF);
    fft_kernel<<<B_ * N_ / 2, 256>>>(out + SEED_OFF, fre, fim, out + FREQ_OFF);
    fused_kernel<<<PGRID, FTH, SMEM_BYTES>>>(
        out + SEED_OFF, mask, x, out + FREQ_OFF,
        gw1, gw2, gb2, gw3, gb3,
        gcw1, gcb1, gcw2, gcb2,
        out + GCN_OFF, out + IMP_OFF, out + COMP_OFF, out + GATE_OFF);
}